// round 13
// baseline (speedup 1.0000x reference)
#include <cuda_runtime.h>
#include <cuda_fp16.h>
#include <math.h>
#include <stdint.h>

#define BNUM 32
#define NTOK 4096
#define FDIN 768
#define DD 256
#define NS 8
#define MROWS (BNUM * NTOK)   // 131072
#define SROWS (BNUM * NS)     // 768 slot rows
#define ITERS 3

// ---------------- scratch (static __device__ — no allocation) ----------------
__device__ float  g_mean[MROWS];
__device__ float  g_rstd[MROWS];
__device__ __half g_inh[(size_t)MROWS * FDIN];
__device__ __half g_h1h[(size_t)MROWS * FDIN];
__device__ __half g_h2h[(size_t)MROWS * DD];      // h2 fp16
__device__ __half g_featsh[(size_t)MROWS * DD];
__device__ __half g_kvh[(size_t)MROWS * 2 * DD];  // [row][512]: keys | vals fp16
__device__ __half g_w1h[FDIN * FDIN];             // [N=768][K=768], scaled by ln1g
__device__ float  g_gB[FDIN];
__device__ float  g_bBp[FDIN];
__device__ __half g_w2h[DD * FDIN];               // [N=256][K=768]
__device__ __half g_wkvh[2 * DD * DD];            // [N=512][K=256]
__device__ float  g_wqT[DD * DD];
// GRU / MLP weights fp16 (K-major)
__device__ __half g_wihh[3 * DD * DD];
__device__ __half g_whhh[3 * DD * DD];
__device__ __half g_mw1h[4 * DD * DD];
__device__ __half g_mw2h[DD * 4 * DD];
// iteration state
__device__ float  g_slots[SROWS * DD];
__device__ __half g_slotsh[SROWS * DD];
__device__ float  g_q[SROWS * DD];
__device__ float  g_U[SROWS * DD];
__device__ float  g_rowsum[SROWS];
__device__ __half g_updh[SROWS * DD];
__device__ float  g_gi[SROWS * 3 * DD];
__device__ float  g_gh[SROWS * 3 * DD];
__device__ float  g_hbuf[SROWS * DD];
__device__ __half g_mlpinh[SROWS * DD];
__device__ __half g_hhh[SROWS * 4 * DD];

// ================= asm helpers =================
#define CP_ASYNC16(dst, src) \
    asm volatile("cp.async.cg.shared.global [%0], [%1], 16;\n" :: "r"(dst), "l"(src))
#define CP_COMMIT() asm volatile("cp.async.commit_group;\n" ::: "memory")
#define CP_WAIT1()  asm volatile("cp.async.wait_group 1;\n" ::: "memory")

__device__ __forceinline__ void ldmx4(uint32_t& r0, uint32_t& r1, uint32_t& r2,
                                      uint32_t& r3, uint32_t addr) {
    asm volatile("ldmatrix.sync.aligned.m8n8.x4.shared.b16 {%0,%1,%2,%3}, [%4];"
                 : "=r"(r0), "=r"(r1), "=r"(r2), "=r"(r3) : "r"(addr));
}

__device__ __forceinline__ void mma_f16(float* c, const uint32_t* a, const uint32_t* b) {
    asm volatile(
        "mma.sync.aligned.m16n8k16.row.col.f32.f16.f16.f32 "
        "{%0,%1,%2,%3}, {%4,%5,%6,%7}, {%8,%9}, {%0,%1,%2,%3};"
        : "+f"(c[0]), "+f"(c[1]), "+f"(c[2]), "+f"(c[3])
        : "r"(a[0]), "r"(a[1]), "r"(a[2]), "r"(a[3]), "r"(b[0]), "r"(b[1]));
}

// ================= big-tile fp16 GEMM: 128x128, BK=64, 2 CTAs/SM =============
// EPI 1: LN-fold+relu -> fp16. EPI 3: raw -> fp16. EPI 4: +bias -> fp16.
#define HR128 72
#define STG128_BYTES (256 * HR128 * 2)    // 36864
#define H128_DSMEM (3 * STG128_BYTES)     // 110592

template<int EPI>
__global__ void __launch_bounds__(256)
hgemm128_kernel(const __half* __restrict__ A, const __half* __restrict__ Bw,
                int Nn, int K, __half* __restrict__ Ch,
                const float* __restrict__ bias) {
    extern __shared__ __align__(16) __half smh[];
    uint32_t smb;
    asm("{ .reg .u64 t; cvta.to.shared.u64 t, %1; cvt.u32.u64 %0, t; }"
        : "=r"(smb) : "l"(smh));

    int tid = threadIdx.x;
    int lane = tid & 31;
    int warp = tid >> 5;
    int grp = lane >> 2, tig = lane & 3;
    int wm = (warp & 3) * 32;
    int wn = (warp >> 2) * 64;
    int bm = blockIdx.y * 128;
    int bn = blockIdx.x * 128;

    const __half* Abm = A + (size_t)bm * K;
    const __half* Bbn = Bw + (size_t)bn * K;

    float acc[2][8][4];
    #pragma unroll
    for (int mt = 0; mt < 2; mt++)
        #pragma unroll
        for (int nt = 0; nt < 8; nt++)
            #pragma unroll
            for (int i = 0; i < 4; i++) acc[mt][nt][i] = 0.f;

    int nit = K / 64;
    #pragma unroll
    for (int s = 0; s < 2; s++) {
        uint32_t base = smb + s * STG128_BYTES;
        #pragma unroll
        for (int j = 0; j < 4; j++) {
            int e = tid + j * 256;
            int r = e >> 3, c = e & 7;
            CP_ASYNC16(base + (r * HR128 + c * 8) * 2,
                       Abm + (size_t)r * K + s * 64 + c * 8);
            CP_ASYNC16(base + (128 * HR128 + r * HR128 + c * 8) * 2,
                       Bbn + (size_t)r * K + s * 64 + c * 8);
        }
        CP_COMMIT();
    }

    for (int it = 0; it < nit; it++) {
        CP_WAIT1();
        __syncthreads();
        uint32_t sa = smb + (it % 3) * STG128_BYTES;
        uint32_t sb = sa + 128 * HR128 * 2;
        if (it + 2 < nit) {
            uint32_t base = smb + ((it + 2) % 3) * STG128_BYTES;
            #pragma unroll
            for (int j = 0; j < 4; j++) {
                int e = tid + j * 256;
                int r = e >> 3, c = e & 7;
                CP_ASYNC16(base + (r * HR128 + c * 8) * 2,
                           Abm + (size_t)r * K + (it + 2) * 64 + c * 8);
                CP_ASYNC16(base + (128 * HR128 + r * HR128 + c * 8) * 2,
                           Bbn + (size_t)r * K + (it + 2) * 64 + c * 8);
            }
        }
        CP_COMMIT();

        #pragma unroll
        for (int kc = 0; kc < 4; kc++) {
            uint32_t afr[2][4], bfr[8][2];
            #pragma unroll
            for (int mt = 0; mt < 2; mt++) {
                uint32_t addr = sa + ((wm + mt * 16 + (lane & 15)) * HR128
                                      + kc * 16 + (lane >> 4) * 8) * 2;
                ldmx4(afr[mt][0], afr[mt][1], afr[mt][2], afr[mt][3], addr);
            }
            #pragma unroll
            for (int ng = 0; ng < 4; ng++) {
                uint32_t r0, r1, r2, r3;
                uint32_t addr = sb + ((wn + ng * 16 + (lane & 15)) * HR128
                                      + kc * 16 + (lane >> 4) * 8) * 2;
                ldmx4(r0, r1, r2, r3, addr);
                bfr[2 * ng][0] = r0; bfr[2 * ng + 1][0] = r1;
                bfr[2 * ng][1] = r2; bfr[2 * ng + 1][1] = r3;
            }
            #pragma unroll
            for (int mt = 0; mt < 2; mt++)
                #pragma unroll
                for (int nt = 0; nt < 8; nt++)
                    mma_f16(acc[mt][nt], afr[mt], bfr[nt]);
        }
    }

    #pragma unroll
    for (int mt = 0; mt < 2; mt++) {
        int r0 = bm + wm + mt * 16 + grp;
        float mu0 = 0.f, rs0 = 0.f, mu1 = 0.f, rs1 = 0.f;
        if (EPI == 1) {
            mu0 = g_mean[r0]; rs0 = g_rstd[r0];
            mu1 = g_mean[r0 + 8]; rs1 = g_rstd[r0 + 8];
        }
        #pragma unroll
        for (int nt = 0; nt < 8; nt++) {
            int col = bn + wn + nt * 8 + tig * 2;
            float c0 = acc[mt][nt][0], c1 = acc[mt][nt][1];
            float c2 = acc[mt][nt][2], c3 = acc[mt][nt][3];
            if (EPI == 1) {
                float gb0 = __ldg(&g_gB[col]), gb1 = __ldg(&g_gB[col + 1]);
                float bb0 = __ldg(&g_bBp[col]), bb1 = __ldg(&g_bBp[col + 1]);
                c0 = fmaxf(c0 * rs0 - mu0 * rs0 * gb0 + bb0, 0.f);
                c1 = fmaxf(c1 * rs0 - mu0 * rs0 * gb1 + bb1, 0.f);
                c2 = fmaxf(c2 * rs1 - mu1 * rs1 * gb0 + bb0, 0.f);
                c3 = fmaxf(c3 * rs1 - mu1 * rs1 * gb1 + bb1, 0.f);
            } else if (EPI == 4) {
                float b0 = __ldg(&bias[col]), b1 = __ldg(&bias[col + 1]);
                c0 += b0; c1 += b1; c2 += b0; c3 += b1;
            }
            *(__half2*)(Ch + (size_t)r0 * Nn + col)       = __floats2half2_rn(c0, c1);
            *(__half2*)(Ch + (size_t)(r0 + 8) * Nn + col) = __floats2half2_rn(c2, c3);
        }
    }
}

// ================= small-tile fp16 GEMM (slot path): 128x64, BK=32 ===========
#define HROW 40
#define STG64_BYTES ((128 + 64) * HROW * 2)
#define H64_DSMEM (3 * STG64_BYTES)

template<int EPI>
__global__ void __launch_bounds__(256, 3)
hgemm64_kernel(const __half* __restrict__ A, const __half* __restrict__ Bw,
               int Nn, int K, float* __restrict__ Cf, __half* __restrict__ Ch,
               const float* __restrict__ bias, const float* __restrict__ res) {
    extern __shared__ __align__(16) __half smh[];
    uint32_t smb;
    asm("{ .reg .u64 t; cvta.to.shared.u64 t, %1; cvt.u32.u64 %0, t; }"
        : "=r"(smb) : "l"(smh));

    int tid = threadIdx.x;
    int lane = tid & 31;
    int warp = tid >> 5;
    int grp = lane >> 2, tig = lane & 3;
    int wm = (warp & 3) * 32;
    int wn = (warp >> 2) * 32;
    int bm = blockIdx.y * 128;
    int bn = blockIdx.x * 64;

    const __half* Abm = A + (size_t)bm * K;
    const __half* Bbn = Bw + (size_t)bn * K;

    float acc[2][4][4];
    #pragma unroll
    for (int mt = 0; mt < 2; mt++)
        #pragma unroll
        for (int nt = 0; nt < 4; nt++)
            #pragma unroll
            for (int i = 0; i < 4; i++) acc[mt][nt][i] = 0.f;

    int nit = K / 32;
    #pragma unroll
    for (int s = 0; s < 2; s++) {
        uint32_t base = smb + s * STG64_BYTES;
        #pragma unroll
        for (int j = 0; j < 2; j++) {
            int e = tid + j * 256;
            int r = e >> 2, c = e & 3;
            CP_ASYNC16(base + (r * HROW + c * 8) * 2, Abm + (size_t)r * K + s * 32 + c * 8);
        }
        {
            int r = tid >> 2, c = tid & 3;
            CP_ASYNC16(base + (128 * HROW + r * HROW + c * 8) * 2,
                       Bbn + (size_t)r * K + s * 32 + c * 8);
        }
        CP_COMMIT();
    }

    for (int it = 0; it < nit; it++) {
        CP_WAIT1();
        __syncthreads();
        uint32_t sa = smb + (it % 3) * STG64_BYTES;
        uint32_t sb = sa + 128 * HROW * 2;
        if (it + 2 < nit) {
            uint32_t base = smb + ((it + 2) % 3) * STG64_BYTES;
            #pragma unroll
            for (int j = 0; j < 2; j++) {
                int e = tid + j * 256;
                int r = e >> 2, c = e & 3;
                CP_ASYNC16(base + (r * HROW + c * 8) * 2,
                           Abm + (size_t)r * K + (it + 2) * 32 + c * 8);
            }
            {
                int r = tid >> 2, c = tid & 3;
                CP_ASYNC16(base + (128 * HROW + r * HROW + c * 8) * 2,
                           Bbn + (size_t)r * K + (it + 2) * 32 + c * 8);
            }
        }
        CP_COMMIT();

        #pragma unroll
        for (int kc = 0; kc < 2; kc++) {
            uint32_t afr[2][4], bfr[4][2];
            #pragma unroll
            for (int mt = 0; mt < 2; mt++) {
                uint32_t addr = sa + ((wm + mt * 16 + (lane & 15)) * HROW
                                      + kc * 16 + (lane >> 4) * 8) * 2;
                ldmx4(afr[mt][0], afr[mt][1], afr[mt][2], afr[mt][3], addr);
            }
            #pragma unroll
            for (int ng = 0; ng < 2; ng++) {
                uint32_t r0, r1, r2, r3;
                uint32_t addr = sb + ((wn + ng * 16 + (lane & 15)) * HROW
                                      + kc * 16 + (lane >> 4) * 8) * 2;
                ldmx4(r0, r1, r2, r3, addr);
                bfr[2 * ng][0] = r0; bfr[2 * ng + 1][0] = r1;
                bfr[2 * ng][1] = r2; bfr[2 * ng + 1][1] = r3;
            }
            #pragma unroll
            for (int mt = 0; mt < 2; mt++)
                #pragma unroll
                for (int nt = 0; nt < 4; nt++)
                    mma_f16(acc[mt][nt], afr[mt], bfr[nt]);
        }
    }

    #pragma unroll
    for (int mt = 0; mt < 2; mt++) {
        int r0 = bm + wm + mt * 16 + grp;
        #pragma unroll
        for (int nt = 0; nt < 4; nt++) {
            int col = bn + wn + nt * 8 + tig * 2;
            float b0 = __ldg(&bias[col]), b1 = __ldg(&bias[col + 1]);
            float c0 = acc[mt][nt][0] + b0, c1 = acc[mt][nt][1] + b1;
            float c2 = acc[mt][nt][2] + b0, c3 = acc[mt][nt][3] + b1;
            if (EPI == 10) {
                *(float2*)(Cf + (size_t)r0 * Nn + col)       = make_float2(c0, c1);
                *(float2*)(Cf + (size_t)(r0 + 8) * Nn + col) = make_float2(c2, c3);
            } else if (EPI == 11) {
                c0 = fmaxf(c0, 0.f); c1 = fmaxf(c1, 0.f);
                c2 = fmaxf(c2, 0.f); c3 = fmaxf(c3, 0.f);
                *(__half2*)(Ch + (size_t)r0 * Nn + col)       = __floats2half2_rn(c0, c1);
                *(__half2*)(Ch + (size_t)(r0 + 8) * Nn + col) = __floats2half2_rn(c2, c3);
            } else {   // EPI 12: residual + dual store
                float2 ra = *(const float2*)(res + (size_t)r0 * Nn + col);
                float2 rb = *(const float2*)(res + (size_t)(r0 + 8) * Nn + col);
                c0 += ra.x; c1 += ra.y; c2 += rb.x; c3 += rb.y;
                *(float2*)(Cf + (size_t)r0 * Nn + col)       = make_float2(c0, c1);
                *(float2*)(Cf + (size_t)(r0 + 8) * Nn + col) = make_float2(c2, c3);
                *(__half2*)(Ch + (size_t)r0 * Nn + col)       = __floats2half2_rn(c0, c1);
                *(__half2*)(Ch + (size_t)(r0 + 8) * Nn + col) = __floats2half2_rn(c2, c3);
            }
        }
    }
}

// ================= prep / small kernels =================
__global__ void ln_stats_f2h_kernel(const float* __restrict__ x, __half* __restrict__ xh) {
    int row = blockIdx.x * 8 + (threadIdx.x >> 5);
    int lane = threadIdx.x & 31;
    const float* p = x + (size_t)row * FDIN;
    __half* ph = xh + (size_t)row * FDIN;
    float v[24];
    float s = 0.f, ss = 0.f;
    #pragma unroll
    for (int k = 0; k < 24; k++) {
        v[k] = p[lane + 32 * k];
        s += v[k];
        ss += v[k] * v[k];
    }
    #pragma unroll
    for (int k = 0; k < 24; k++) ph[lane + 32 * k] = __float2half(v[k]);
    #pragma unroll
    for (int o = 16; o; o >>= 1) {
        s  += __shfl_xor_sync(0xffffffffu, s, o);
        ss += __shfl_xor_sync(0xffffffffu, ss, o);
    }
    float m = s * (1.f / FDIN);
    float var = ss * (1.f / FDIN) - m * m;
    if (lane == 0) { g_mean[row] = m; g_rstd[row] = rsqrtf(var + 1e-5f); }
}

__global__ void conv_f2h_kernel(const float* __restrict__ in, __half* __restrict__ out) {
    size_t i = ((size_t)blockIdx.x * 256 + threadIdx.x) * 4;
    float4 v = *(const float4*)(in + i);
    *(__half2*)(out + i)     = __floats2half2_rn(v.x, v.y);
    *(__half2*)(out + i + 2) = __floats2half2_rn(v.z, v.w);
}

__global__ void trans_h_kernel(const float* __restrict__ in, __half* __restrict__ out,
                               int R, int C, const float* __restrict__ scale) {
    __shared__ float t[32][33];
    int bx = blockIdx.x * 32, by = blockIdx.y * 32;
    int x = bx + threadIdx.x;
    #pragma unroll
    for (int j = 0; j < 32; j += 8) {
        int y = by + threadIdx.y + j;
        float s = scale ? scale[y] : 1.f;
        t[threadIdx.y + j][threadIdx.x] = in[(size_t)y * C + x] * s;
    }
    __syncthreads();
    int x2 = by + threadIdx.x;
    #pragma unroll
    for (int j = 0; j < 32; j += 8) {
        int y2 = bx + threadIdx.y + j;
        out[(size_t)y2 * R + x2] = __float2half(t[threadIdx.x][threadIdx.y + j]);
    }
}

__global__ void trans_f_kernel(const float* __restrict__ in, float* __restrict__ out,
                               int R, int C) {
    __shared__ float t[32][33];
    int bx = blockIdx.x * 32, by = blockIdx.y * 32;
    int x = bx + threadIdx.x;
    #pragma unroll
    for (int j = 0; j < 32; j += 8)
        t[threadIdx.y + j][threadIdx.x] = in[(size_t)(by + threadIdx.y + j) * C + x];
    __syncthreads();
    int x2 = by + threadIdx.x;
    #pragma unroll
    for (int j = 0; j < 32; j += 8)
        out[(size_t)(bx + threadIdx.y + j) * R + x2] = t[threadIdx.x][threadIdx.y + j];
}

__global__ void wkv_h_kernel(const float* __restrict__ wk, const float* __restrict__ wv) {
    int i = blockIdx.x * 256 + threadIdx.x;
    g_wkvh[i] = __float2half(wk[i]);
    g_wkvh[DD * DD + i] = __float2half(wv[i]);
}

// coalesced prep_sums: grid (FDIN/256, 8); k-split with atomics (gB/bBp pre-zeroed)
__global__ void prep_sums_kernel(const float* __restrict__ w1,
                                 const float* __restrict__ g,
                                 const float* __restrict__ b,
                                 const float* __restrict__ b1) {
    int n = blockIdx.x * 256 + threadIdx.x;
    int k0 = blockIdx.y * 96;
    float s1 = 0.f, s2 = 0.f;
    #pragma unroll 8
    for (int k = k0; k < k0 + 96; k++) {
        float w = w1[(size_t)k * FDIN + n];
        s1 += g[k] * w;
        s2 += b[k] * w;
    }
    if (blockIdx.y == 0) s2 += b1[n];
    atomicAdd(&g_gB[n], s1);
    atomicAdd(&g_bBp[n], s2);
}

__global__ void slots_init_kernel(const float* __restrict__ si) {
    int i = blockIdx.x * 256 + threadIdx.x;
    float v = si[i & (NS * DD - 1)];
    g_slots[i] = v;
    g_slotsh[i] = __float2half(v);
}

__device__ __forceinline__ float2 block_meanvar_256(float v, float* r1, float* r2) {
    float s = v, q = v * v;
    #pragma unroll
    for (int o = 16; o; o >>= 1) {
        s += __shfl_xor_sync(0xffffffffu, s, o);
        q += __shfl_xor_sync(0xffffffffu, q, o);
    }
    int w = threadIdx.x >> 5, lane = threadIdx.x & 31;
    if (lane == 0) { r1[w] = s; r2[w] = q; }
    __syncthreads();
    float sum = 0.f, sq = 0.f;
    #pragma unroll
    for (int i = 0; i < 8; i++) { sum += r1[i]; sq += r2[i]; }
    __syncthreads();
    float m = sum * (1.f / 256.f);
    float var = sq * (1.f / 256.f) - m * m;
    return make_float2(m, rsqrtf(var + 1e-5f));
}

// feats = (half) LN(h2h): warp per row (fp16 in/out), 8 rows/block
__global__ void ln256h_kernel(const __half* __restrict__ x, __half* __restrict__ y,
                              const float* __restrict__ g, const float* __restrict__ b) {
    size_t row = (size_t)blockIdx.x * 8 + (threadIdx.x >> 5);
    int lane = threadIdx.x & 31;
    const __half* p = x + row * DD;
    // 8 halves per lane: one 16B load
    __half2 h4[4];
    *(uint4*)h4 = *(const uint4*)(p + lane * 8);
    float v[8];
    #pragma unroll
    for (int k = 0; k < 4; k++) {
        float2 f = __half22float2(h4[k]);
        v[2 * k] = f.x; v[2 * k + 1] = f.y;
    }
    float s = 0.f, q = 0.f;
    #pragma unroll
    for (int k = 0; k < 8; k++) { s += v[k]; q += v[k] * v[k]; }
    #pragma unroll
    for (int o = 16; o; o >>= 1) {
        s += __shfl_xor_sync(0xffffffffu, s, o);
        q += __shfl_xor_sync(0xffffffffu, q, o);
    }
    float m = s * (1.f / 256.f);
    float rs = rsqrtf(q * (1.f / 256.f) - m * m + 1e-5f);
    int c0 = lane * 8;
    __half2 o4[4];
    #pragma unroll
    for (int k = 0; k < 4; k++) {
        int c = c0 + 2 * k;
        o4[k] = __floats2half2_rn(
            (v[2 * k] - m) * rs * __ldg(&g[c]) + __ldg(&b[c]),
            (v[2 * k + 1] - m) * rs * __ldg(&g[c + 1]) + __ldg(&b[c + 1]));
    }
    *(uint4*)(y + row * DD + c0) = *(uint4*)o4;
}

__global__ void qproj_kernel(const float* __restrict__ ng, const float* __restrict__ nb) {
    __shared__ float sln[DD];
    __shared__ float r1[8], r2[8];
    int row = blockIdx.x, tid = threadIdx.x;
    float v = g_slots[row * DD + tid];
    float2 mv = block_meanvar_256(v, r1, r2);
    sln[tid] = (v - mv.x) * mv.y * ng[tid] + nb[tid];
    g_U[row * DD + tid] = 0.f;
    if (tid == 0) g_rowsum[row] = 0.f;
    __syncthreads();
    float acc = 0.f;
    #pragma unroll 8
    for (int d = 0; d < DD; d++) acc += sln[d] * g_wqT[d * DD + tid];
    g_q[row * DD + tid] = acc;
}

__global__ void __launch_bounds__(256)
attn_kernel() {
    int b = blockIdx.x, ch = blockIdx.y;
    int warp = threadIdx.x >> 5, lane = threadIdx.x & 31;
    __shared__ float qs[NS * DD];
    __shared__ float dots[8][NS];
    __shared__ float aw[8][NS];
    for (int i = threadIdx.x; i < NS * DD; i += 256) qs[i] = g_q[b * NS * DD + i];
    __syncthreads();
    float qreg[8];
    #pragma unroll
    for (int k = 0; k < 4; k++) {
        qreg[2 * k]     = qs[warp * DD + 2 * (lane + 32 * k)];
        qreg[2 * k + 1] = qs[warp * DD + 2 * (lane + 32 * k) + 1];
    }
    float2 uacc[4];
    #pragma unroll
    for (int k = 0; k < 4; k++) uacc[k] = make_float2(0.f, 0.f);
    float rsum = 0.f;
    const float scale = 0.0625f;
    int t0 = ch * 256;
    const __half* kvb = g_kvh + ((size_t)b * NTOK + t0) * 512;

    for (int tt = 0; tt < 256; tt += 8) {
        #pragma unroll
        for (int u = 0; u < 8; u++) {
            const __half2* kp = (const __half2*)(kvb + (size_t)(tt + u) * 512);
            float d = 0.f;
            #pragma unroll
            for (int k = 0; k < 4; k++) {
                float2 kv2 = __half22float2(kp[lane + 32 * k]);
                d += qreg[2 * k] * kv2.x + qreg[2 * k + 1] * kv2.y;
            }
            #pragma unroll
            for (int o = 16; o; o >>= 1) d += __shfl_xor_sync(0xffffffffu, d, o);
            if (lane == 0) dots[u][warp] = d * scale;
        }
        __syncthreads();
        if (threadIdx.x < 64) {
            int u = threadIdx.x >> 3, s = threadIdx.x & 7;
            float mx = -1e30f;
            #pragma unroll
            for (int s2 = 0; s2 < NS; s2++) mx = fmaxf(mx, dots[u][s2]);
            float e = expf(dots[u][s] - mx);
            float sum = e;
            #pragma unroll
            for (int o = 1; o < 8; o <<= 1) sum += __shfl_xor_sync(0xffffffffu, sum, o);
            aw[u][s] = e / sum + 1e-8f;
        }
        __syncthreads();
        #pragma unroll
        for (int u = 0; u < 8; u++) {
            float a = aw[u][warp];
            const __half2* vp = (const __half2*)(kvb + (size_t)(tt + u) * 512 + 256);
            #pragma unroll
            for (int k = 0; k < 4; k++) {
                float2 vv = __half22float2(vp[lane + 32 * k]);
                uacc[k].x += a * vv.x;
                uacc[k].y += a * vv.y;
            }
            rsum += a;
        }
        __syncthreads();
    }
    float* up = g_U + (b * NS + warp) * DD;
    #pragma unroll
    for (int k = 0; k < 4; k++) {
        atomicAdd(&up[2 * (lane + 32 * k)], uacc[k].x);
        atomicAdd(&up[2 * (lane + 32 * k) + 1], uacc[k].y);
    }
    if (lane == 0) atomicAdd(&g_rowsum[b * NS + warp], rsum);
}

__global__ void updfin_kernel() {
    int i = blockIdx.x * 256 + threadIdx.x;
    g_updh[i] = __float2half(g_U[i] / g_rowsum[i >> 8]);
}

__global__ void gru_pw_kernel(const float* __restrict__ mlng,
                              const float* __restrict__ mlnb) {
    __shared__ float r1[8], r2[8];
    int row = blockIdx.x, tid = threadIdx.x;
    const float* gi = g_gi + row * 3 * DD;
    const float* gh = g_gh + row * 3 * DD;
    float ir = gi[tid], iz = gi[tid + 256], inn = gi[tid + 512];
    float hr = gh[tid], hz = gh[tid + 256], hn = gh[tid + 512];
    float sprev = g_slots[row * DD + tid];
    float r = 1.f / (1.f + expf(-(ir + hr)));
    float z = 1.f / (1.f + expf(-(iz + hz)));
    float n = tanhf(inn + r * hn);
    float h = (1.f - z) * n + z * sprev;
    g_hbuf[row * DD + tid] = h;
    float2 mv = block_meanvar_256(h, r1, r2);
    g_mlpinh[row * DD + tid] = __float2half((h - mv.x) * mv.y * mlng[tid] + mlnb[tid]);
}

// ================= launch =================
extern "C" void kernel_launch(void* const* d_in, const int* in_sizes, int n_in,
                              void* d_out, int out_size) {
    const float* inputs   = (const float*)d_in[0];
    const float* slots_in = (const float*)d_in[1];
    const float* ln1g = (const float*)d_in[2];
    const float* ln1b = (const float*)d_in[3];
    const float* w1   = (const float*)d_in[4];
    const float* b1   = (const float*)d_in[5];
    const float* w2   = (const float*)d_in[6];
    const float* b2   = (const float*)d_in[7];
    const float* ln2g = (const float*)d_in[8];
    const float* ln2b = (const float*)d_in[9];
    const float* wq   = (const float*)d_in[10];
    const float* wk   = (const float*)d_in[11];
    const float* wv   = (const float*)d_in[12];
    const float* normg = (const float*)d_in[13];
    const float* normb = (const float*)d_in[14];
    const float* gwih = (const float*)d_in[15];
    const float* gwhh = (const float*)d_in[16];
    const float* gbih = (const float*)d_in[17];
    const float* gbhh = (const float*)d_in[18];
    const float* mlng = (const float*)d_in[19];
    const float* mlnb = (const float*)d_in[20];
    const float* mw1  = (const float*)d_in[21];
    const float* mb1  = (const float*)d_in[22];
    const float* mw2  = (const float*)d_in[23];
    const float* mb2  = (const float*)d_in[24];
    float* out = (float*)d_out;

    __half *p_inh, *p_h1h, *p_h2h, *p_featsh, *p_kvh, *p_w1h, *p_w2h, *p_wkvh;
    __half *p_wihh, *p_whhh, *p_mw1h, *p_mw2h, *p_updh, *p_mlpinh, *p_hhh, *p_slotsh;
    float *p_wqT, *p_slots, *p_gi, *p_gh, *p_hbuf, *p_gB, *p_bBp;
    cudaGetSymbolAddress((void**)&p_inh,    g_inh);
    cudaGetSymbolAddress((void**)&p_h1h,    g_h1h);
    cudaGetSymbolAddress((void**)&p_h2h,    g_h2h);
    cudaGetSymbolAddress((void**)&p_featsh, g_featsh);
    cudaGetSymbolAddress((void**)&p_kvh,    g_kvh);
    cudaGetSymbolAddress((void**)&p_w1h,    g_w1h);
    cudaGetSymbolAddress((void**)&p_w2h,    g_w2h);
    cudaGetSymbolAddress((void**)&p_wkvh,   g_wkvh);
    cudaGetSymbolAddress((void**)&p_wihh,   g_wihh);
    cudaGetSymbolAddress((void**)&p_whhh,   g_whhh);
    cudaGetSymbolAddress((void**)&p_mw1h,   g_mw1h);
    cudaGetSymbolAddress((void**)&p_mw2h,   g_mw2h);
    cudaGetSymbolAddress((void**)&p_updh,   g_updh);
    cudaGetSymbolAddress((void**)&p_mlpinh, g_mlpinh);
    cudaGetSymbolAddress((void**)&p_hhh,    g_hhh);
    cudaGetSymbolAddress((void**)&p_slotsh, g_slotsh);
    cudaGetSymbolAddress((void**)&p_wqT,    g_wqT);
    cudaGetSymbolAddress((void**)&p_slots,  g_slots);
    cudaGetSymbolAddress((void**)&p_gi,     g_gi);
    cudaGetSymbolAddress((void**)&p_gh,     g_gh);
    cudaGetSymbolAddress((void**)&p_hbuf,   g_hbuf);
    cudaGetSymbolAddress((void**)&p_gB,     g_gB);
    cudaGetSymbolAddress((void**)&p_bBp,    g_bBp);

    // smem opt-ins (above 48 KB default)
    cudaFuncSetAttribute(hgemm128_kernel<1>, cudaFuncAttributeMaxDynamicSharedMemorySize, H128_DSMEM);
    cudaFuncSetAttribute(hgemm128_kernel<3>, cudaFuncAttributeMaxDynamicSharedMemorySize, H128_DSMEM);
    cudaFuncSetAttribute(hgemm128_kernel<4>, cudaFuncAttributeMaxDynamicSharedMemorySize, H128_DSMEM);

    dim3 tb(32, 8);
    cudaMemsetAsync(p_gB, 0, FDIN * sizeof(float));
    cudaMemsetAsync(p_bBp, 0, FDIN * sizeof(float));
    // 0: fused LN stats + fp16 conversion of inputs
    ln_stats_f2h_kernel<<<MROWS / 8, 256>>>(inputs, p_inh);
    // 1: w1 -> [N][K] fp16 scaled by ln1g
    trans_h_kernel<<<dim3(FDIN / 32, FDIN / 32), tb>>>(w1, p_w1h, FDIN, FDIN, ln1g);
    // 2: epilogue fold vectors (coalesced, k-split atomics)
    prep_sums_kernel<<<dim3(FDIN / 256, 8), 256>>>(w1, ln1g, ln1b, b1);
    // 3: GEMM1 (128x128 tile, BK=64)   << ncu window
    hgemm128_kernel<1><<<dim3(FDIN / 128, MROWS / 128), 256, H128_DSMEM>>>(
        p_inh, p_w1h, FDIN, FDIN, p_h1h, nullptr);
    // 4: w2 -> [N][K] fp16
    trans_h_kernel<<<dim3(DD / 32, FDIN / 32), tb>>>(w2, p_w2h, FDIN, DD, nullptr);
    // 5: GEMM2 h2 = h1 @ w2 + b2 -> fp16 (2-CTA kernel)
    hgemm128_kernel<4><<<dim3(DD / 128, MROWS / 128), 256, H128_DSMEM>>>(
        p_h1h, p_w2h, DD, FDIN, p_h2h, b2);
    // 6: feats = LN(h2h) -> fp16 (warp-per-row, fp16 traffic)
    ln256h_kernel<<<MROWS / 8, 256>>>(p_h2h, p_featsh, ln2g, ln2b);
    // 7: wk|wv -> fp16
    wkv_h_kernel<<<DD * DD / 256, 256>>>(wk, wv);
    // 8: KV GEMM -> fp16
    hgemm128_kernel<3><<<dim3(2 * DD / 128, MROWS / 128), 256, H128_DSMEM>>>(
        p_featsh, p_wkvh, 2 * DD, DD, p_kvh, nullptr);

    // slot-path weight prep
    trans_f_kernel<<<dim3(DD / 32, DD / 32), tb>>>(wq, p_wqT, DD, DD);
    conv_f2h_kernel<<<3 * DD * DD / 1024, 256>>>(gwih, p_wihh);
    conv_f2h_kernel<<<3 * DD * DD / 1024, 256>>>(gwhh, p_whhh);
    trans_h_kernel<<<dim3(4 * DD / 32, DD / 32), tb>>>(mw1, p_mw1h, DD, 4 * DD, nullptr);
    trans_h_kernel<<<dim3(DD / 32, 4 * DD / 32), tb>>>(mw2, p_mw2h, 4 * DD, DD, nullptr);
    slots_init_kernel<<<SROWS * DD / 256, 256>>>(slots_in);

    for (int t = 0; t < ITERS; t++) {
        qproj_kernel<<<SROWS, 256>>>(normg, normb);
        attn_kernel<<<dim3(BNUM, 16), 256>>>();
        updfin_kernel<<<SROWS, 256>>>();
        hgemm64_kernel<10><<<dim3(3 * DD / 64, SROWS / 128), 256, H64_DSMEM>>>(
            p_updh, p_wihh, 3 * DD, DD, p_gi, nullptr, gbih, nullptr);
        hgemm64_kernel<10><<<dim3(3 * DD / 64, SROWS / 128), 256, H64_DSMEM>>>(
            p_slotsh, p_whhh, 3 * DD, DD, p_gh, nullptr, gbhh, nullptr);
        gru_pw_kernel<<<SROWS, 256>>>(mlng, mlnb);
        hgemm64_kernel<11><<<dim3(4 * DD / 64, SROWS / 128), 256, H64_DSMEM>>>(
            p_mlpinh, p_mw1h, 4 * DD, DD, nullptr, p_hhh, mb1, nullptr);
        float* dst = (t == ITERS - 1) ? out : p_slots;
        hgemm64_kernel<12><<<dim3(DD / 64, SROWS / 128), 256, H64_DSMEM>>>(
            p_hhh, p_mw2h, DD, 4 * DD, dst, p_slotsh, mb2, p_hbuf);
    }
}

// round 14
// speedup vs baseline: 1.0387x; 1.0387x over previous
#include <cuda_runtime.h>
#include <cuda_fp16.h>
#include <math.h>
#include <stdint.h>

#define BNUM 32
#define NTOK 4096
#define FDIN 768
#define DD 256
#define NS 8
#define MROWS (BNUM * NTOK)   // 131072
#define SROWS (BNUM * NS)     // 768 slot rows
#define ITERS 3

// ---------------- scratch (static __device__ — no allocation) ----------------
__device__ float  g_mean[MROWS];
__device__ float  g_rstd[MROWS];
__device__ __half g_inh[(size_t)MROWS * FDIN];
__device__ __half g_h1h[(size_t)MROWS * FDIN];
__device__ __half g_featsh[(size_t)MROWS * DD];
__device__ __half g_kvh[(size_t)MROWS * 2 * DD];  // [row][512]: keys | vals fp16
__device__ __half g_w1h[FDIN * FDIN];             // [N=768][K=768], scaled by ln1g
__device__ float  g_gB[FDIN];
__device__ float  g_bBp[FDIN];
__device__ __half g_w2h[DD * FDIN];               // [N=256][K=768]
__device__ __half g_wkvh[2 * DD * DD];            // [N=512][K=256]
__device__ float  g_wqT[DD * DD];
// GRU / MLP weights fp16 (K-major)
__device__ __half g_wihh[3 * DD * DD];
__device__ __half g_whhh[3 * DD * DD];
__device__ __half g_mw1h[4 * DD * DD];
__device__ __half g_mw2h[DD * 4 * DD];
// iteration state
__device__ float  g_slots[SROWS * DD];
__device__ __half g_slotsh[SROWS * DD];
__device__ float  g_q[SROWS * DD];
__device__ float  g_U[SROWS * DD];
__device__ float  g_rowsum[SROWS];
__device__ __half g_updh[SROWS * DD];
__device__ float  g_gi[SROWS * 3 * DD];
__device__ float  g_gh[SROWS * 3 * DD];
__device__ float  g_hbuf[SROWS * DD];
__device__ __half g_mlpinh[SROWS * DD];
__device__ __half g_hhh[SROWS * 4 * DD];

// ================= asm helpers =================
#define CP_ASYNC16(dst, src) \
    asm volatile("cp.async.cg.shared.global [%0], [%1], 16;\n" :: "r"(dst), "l"(src))
#define CP_COMMIT() asm volatile("cp.async.commit_group;\n" ::: "memory")
#define CP_WAIT1()  asm volatile("cp.async.wait_group 1;\n" ::: "memory")

__device__ __forceinline__ void ldmx4(uint32_t& r0, uint32_t& r1, uint32_t& r2,
                                      uint32_t& r3, uint32_t addr) {
    asm volatile("ldmatrix.sync.aligned.m8n8.x4.shared.b16 {%0,%1,%2,%3}, [%4];"
                 : "=r"(r0), "=r"(r1), "=r"(r2), "=r"(r3) : "r"(addr));
}

__device__ __forceinline__ void mma_f16(float* c, const uint32_t* a, const uint32_t* b) {
    asm volatile(
        "mma.sync.aligned.m16n8k16.row.col.f32.f16.f16.f32 "
        "{%0,%1,%2,%3}, {%4,%5,%6,%7}, {%8,%9}, {%0,%1,%2,%3};"
        : "+f"(c[0]), "+f"(c[1]), "+f"(c[2]), "+f"(c[3])
        : "r"(a[0]), "r"(a[1]), "r"(a[2]), "r"(a[3]), "r"(b[0]), "r"(b[1]));
}

// ================= big-tile fp16 GEMM (GEMM1/KV): 128x128, BK=64 ============
// EPI 1: LN-fold+relu -> fp16. EPI 3: raw -> fp16.
#define HR128 72
#define STG128_BYTES (256 * HR128 * 2)    // 36864
#define H128_DSMEM (3 * STG128_BYTES)     // 110592

template<int EPI>
__global__ void __launch_bounds__(256)
hgemm128_kernel(const __half* __restrict__ A, const __half* __restrict__ Bw,
                int Nn, int K, __half* __restrict__ Ch) {
    extern __shared__ __align__(16) __half smh[];
    uint32_t smb;
    asm("{ .reg .u64 t; cvta.to.shared.u64 t, %1; cvt.u32.u64 %0, t; }"
        : "=r"(smb) : "l"(smh));

    int tid = threadIdx.x;
    int lane = tid & 31;
    int warp = tid >> 5;
    int grp = lane >> 2, tig = lane & 3;
    int wm = (warp & 3) * 32;
    int wn = (warp >> 2) * 64;
    int bm = blockIdx.y * 128;
    int bn = blockIdx.x * 128;

    const __half* Abm = A + (size_t)bm * K;
    const __half* Bbn = Bw + (size_t)bn * K;

    float acc[2][8][4];
    #pragma unroll
    for (int mt = 0; mt < 2; mt++)
        #pragma unroll
        for (int nt = 0; nt < 8; nt++)
            #pragma unroll
            for (int i = 0; i < 4; i++) acc[mt][nt][i] = 0.f;

    int nit = K / 64;
    #pragma unroll
    for (int s = 0; s < 2; s++) {
        uint32_t base = smb + s * STG128_BYTES;
        #pragma unroll
        for (int j = 0; j < 4; j++) {
            int e = tid + j * 256;
            int r = e >> 3, c = e & 7;
            CP_ASYNC16(base + (r * HR128 + c * 8) * 2,
                       Abm + (size_t)r * K + s * 64 + c * 8);
            CP_ASYNC16(base + (128 * HR128 + r * HR128 + c * 8) * 2,
                       Bbn + (size_t)r * K + s * 64 + c * 8);
        }
        CP_COMMIT();
    }

    for (int it = 0; it < nit; it++) {
        CP_WAIT1();
        __syncthreads();
        uint32_t sa = smb + (it % 3) * STG128_BYTES;
        uint32_t sb = sa + 128 * HR128 * 2;
        if (it + 2 < nit) {
            uint32_t base = smb + ((it + 2) % 3) * STG128_BYTES;
            #pragma unroll
            for (int j = 0; j < 4; j++) {
                int e = tid + j * 256;
                int r = e >> 3, c = e & 7;
                CP_ASYNC16(base + (r * HR128 + c * 8) * 2,
                           Abm + (size_t)r * K + (it + 2) * 64 + c * 8);
                CP_ASYNC16(base + (128 * HR128 + r * HR128 + c * 8) * 2,
                           Bbn + (size_t)r * K + (it + 2) * 64 + c * 8);
            }
        }
        CP_COMMIT();

        #pragma unroll
        for (int kc = 0; kc < 4; kc++) {
            uint32_t afr[2][4], bfr[8][2];
            #pragma unroll
            for (int mt = 0; mt < 2; mt++) {
                uint32_t addr = sa + ((wm + mt * 16 + (lane & 15)) * HR128
                                      + kc * 16 + (lane >> 4) * 8) * 2;
                ldmx4(afr[mt][0], afr[mt][1], afr[mt][2], afr[mt][3], addr);
            }
            #pragma unroll
            for (int ng = 0; ng < 4; ng++) {
                uint32_t r0, r1, r2, r3;
                uint32_t addr = sb + ((wn + ng * 16 + (lane & 15)) * HR128
                                      + kc * 16 + (lane >> 4) * 8) * 2;
                ldmx4(r0, r1, r2, r3, addr);
                bfr[2 * ng][0] = r0; bfr[2 * ng + 1][0] = r1;
                bfr[2 * ng][1] = r2; bfr[2 * ng + 1][1] = r3;
            }
            #pragma unroll
            for (int mt = 0; mt < 2; mt++)
                #pragma unroll
                for (int nt = 0; nt < 8; nt++)
                    mma_f16(acc[mt][nt], afr[mt], bfr[nt]);
        }
    }

    #pragma unroll
    for (int mt = 0; mt < 2; mt++) {
        int r0 = bm + wm + mt * 16 + grp;
        float mu0 = 0.f, rs0 = 0.f, mu1 = 0.f, rs1 = 0.f;
        if (EPI == 1) {
            mu0 = g_mean[r0]; rs0 = g_rstd[r0];
            mu1 = g_mean[r0 + 8]; rs1 = g_rstd[r0 + 8];
        }
        #pragma unroll
        for (int nt = 0; nt < 8; nt++) {
            int col = bn + wn + nt * 8 + tig * 2;
            float c0 = acc[mt][nt][0], c1 = acc[mt][nt][1];
            float c2 = acc[mt][nt][2], c3 = acc[mt][nt][3];
            if (EPI == 1) {
                float gb0 = __ldg(&g_gB[col]), gb1 = __ldg(&g_gB[col + 1]);
                float bb0 = __ldg(&g_bBp[col]), bb1 = __ldg(&g_bBp[col + 1]);
                c0 = fmaxf(c0 * rs0 - mu0 * rs0 * gb0 + bb0, 0.f);
                c1 = fmaxf(c1 * rs0 - mu0 * rs0 * gb1 + bb1, 0.f);
                c2 = fmaxf(c2 * rs1 - mu1 * rs1 * gb0 + bb0, 0.f);
                c3 = fmaxf(c3 * rs1 - mu1 * rs1 * gb1 + bb1, 0.f);
            }
            *(__half2*)(Ch + (size_t)r0 * Nn + col)       = __floats2half2_rn(c0, c1);
            *(__half2*)(Ch + (size_t)(r0 + 8) * Nn + col) = __floats2half2_rn(c2, c3);
        }
    }
}

// ========== GEMM2 fused row-LN: 128x256 tile, 512 threads, BK=64 ============
#define STG256_BYTES ((128 + 256) * HR128 * 2)   // 55296
#define H256_DSMEM (3 * STG256_BYTES)            // 165888

__global__ void __launch_bounds__(512)
hgemm2ln_kernel(const __half* __restrict__ A, const __half* __restrict__ Bw,
                int K, __half* __restrict__ Ch,
                const float* __restrict__ bias,
                const float* __restrict__ lng, const float* __restrict__ lnb) {
    extern __shared__ __align__(16) __half smh[];
    uint32_t smb;
    asm("{ .reg .u64 t; cvta.to.shared.u64 t, %1; cvt.u32.u64 %0, t; }"
        : "=r"(smb) : "l"(smh));

    const int Nn = 256;
    int tid = threadIdx.x;
    int lane = tid & 31;
    int warp = tid >> 5;
    int grp = lane >> 2, tig = lane & 3;
    int wm = (warp & 3) * 32;
    int wn = (warp >> 2) * 64;
    int bm = blockIdx.y * 128;

    const __half* Abm = A + (size_t)bm * K;
    const __half* Bbn = Bw;

    float acc[2][8][4];
    #pragma unroll
    for (int mt = 0; mt < 2; mt++)
        #pragma unroll
        for (int nt = 0; nt < 8; nt++)
            #pragma unroll
            for (int i = 0; i < 4; i++) acc[mt][nt][i] = 0.f;

    int nit = K / 64;
    #pragma unroll
    for (int s = 0; s < 2; s++) {
        uint32_t base = smb + s * STG256_BYTES;
        #pragma unroll
        for (int j = 0; j < 2; j++) {
            int e = tid + j * 512;
            int r = e >> 3, c = e & 7;
            CP_ASYNC16(base + (r * HR128 + c * 8) * 2,
                       Abm + (size_t)r * K + s * 64 + c * 8);
        }
        #pragma unroll
        for (int j = 0; j < 4; j++) {
            int e = tid + j * 512;
            int r = e >> 3, c = e & 7;
            CP_ASYNC16(base + (128 * HR128 + r * HR128 + c * 8) * 2,
                       Bbn + (size_t)r * K + s * 64 + c * 8);
        }
        CP_COMMIT();
    }

    for (int it = 0; it < nit; it++) {
        CP_WAIT1();
        __syncthreads();
        uint32_t sa = smb + (it % 3) * STG256_BYTES;
        uint32_t sb = sa + 128 * HR128 * 2;
        if (it + 2 < nit) {
            uint32_t base = smb + ((it + 2) % 3) * STG256_BYTES;
            #pragma unroll
            for (int j = 0; j < 2; j++) {
                int e = tid + j * 512;
                int r = e >> 3, c = e & 7;
                CP_ASYNC16(base + (r * HR128 + c * 8) * 2,
                           Abm + (size_t)r * K + (it + 2) * 64 + c * 8);
            }
            #pragma unroll
            for (int j = 0; j < 4; j++) {
                int e = tid + j * 512;
                int r = e >> 3, c = e & 7;
                CP_ASYNC16(base + (128 * HR128 + r * HR128 + c * 8) * 2,
                           Bbn + (size_t)r * K + (it + 2) * 64 + c * 8);
            }
        }
        CP_COMMIT();

        #pragma unroll
        for (int kc = 0; kc < 4; kc++) {
            uint32_t afr[2][4], bfr[8][2];
            #pragma unroll
            for (int mt = 0; mt < 2; mt++) {
                uint32_t addr = sa + ((wm + mt * 16 + (lane & 15)) * HR128
                                      + kc * 16 + (lane >> 4) * 8) * 2;
                ldmx4(afr[mt][0], afr[mt][1], afr[mt][2], afr[mt][3], addr);
            }
            #pragma unroll
            for (int ng = 0; ng < 4; ng++) {
                uint32_t r0, r1, r2, r3;
                uint32_t addr = sb + ((wn + ng * 16 + (lane & 15)) * HR128
                                      + kc * 16 + (lane >> 4) * 8) * 2;
                ldmx4(r0, r1, r2, r3, addr);
                bfr[2 * ng][0] = r0; bfr[2 * ng + 1][0] = r1;
                bfr[2 * ng][1] = r2; bfr[2 * ng + 1][1] = r3;
            }
            #pragma unroll
            for (int mt = 0; mt < 2; mt++)
                #pragma unroll
                for (int nt = 0; nt < 8; nt++)
                    mma_f16(acc[mt][nt], afr[mt], bfr[nt]);
        }
    }

    // ---- fused row-LN epilogue ----
    __syncthreads();
    float* s_sum = (float*)smh;
    float* s_sq  = s_sum + 128;
    float* s_mu  = s_sq + 128;
    float* s_rs  = s_mu + 128;
    if (tid < 128) { s_sum[tid] = 0.f; s_sq[tid] = 0.f; }
    __syncthreads();

    #pragma unroll
    for (int mt = 0; mt < 2; mt++) {
        int rl = wm + mt * 16 + grp;
        float s0 = 0.f, q0 = 0.f, s1 = 0.f, q1 = 0.f;
        #pragma unroll
        for (int nt = 0; nt < 8; nt++) {
            int col = wn + nt * 8 + tig * 2;
            float b0 = __ldg(&bias[col]), b1 = __ldg(&bias[col + 1]);
            float c0 = acc[mt][nt][0] + b0, c1 = acc[mt][nt][1] + b1;
            float c2 = acc[mt][nt][2] + b0, c3 = acc[mt][nt][3] + b1;
            acc[mt][nt][0] = c0; acc[mt][nt][1] = c1;
            acc[mt][nt][2] = c2; acc[mt][nt][3] = c3;
            s0 += c0 + c1; q0 += c0 * c0 + c1 * c1;
            s1 += c2 + c3; q1 += c2 * c2 + c3 * c3;
        }
        #pragma unroll
        for (int o = 1; o < 4; o <<= 1) {
            s0 += __shfl_xor_sync(0xffffffffu, s0, o);
            q0 += __shfl_xor_sync(0xffffffffu, q0, o);
            s1 += __shfl_xor_sync(0xffffffffu, s1, o);
            q1 += __shfl_xor_sync(0xffffffffu, q1, o);
        }
        if (tig == 0) {
            atomicAdd(&s_sum[rl], s0);     atomicAdd(&s_sq[rl], q0);
            atomicAdd(&s_sum[rl + 8], s1); atomicAdd(&s_sq[rl + 8], q1);
        }
    }
    __syncthreads();
    if (tid < 128) {
        float m = s_sum[tid] * (1.f / 256.f);
        float var = s_sq[tid] * (1.f / 256.f) - m * m;
        s_mu[tid] = m;
        s_rs[tid] = rsqrtf(var + 1e-5f);
    }
    __syncthreads();

    #pragma unroll
    for (int mt = 0; mt < 2; mt++) {
        int rl = wm + mt * 16 + grp;
        float mu0 = s_mu[rl], rs0 = s_rs[rl];
        float mu1 = s_mu[rl + 8], rs1 = s_rs[rl + 8];
        int gr = bm + rl;
        #pragma unroll
        for (int nt = 0; nt < 8; nt++) {
            int col = wn + nt * 8 + tig * 2;
            float g0 = __ldg(&lng[col]), g1 = __ldg(&lng[col + 1]);
            float l0 = __ldg(&lnb[col]), l1 = __ldg(&lnb[col + 1]);
            float c0 = (acc[mt][nt][0] - mu0) * rs0 * g0 + l0;
            float c1 = (acc[mt][nt][1] - mu0) * rs0 * g1 + l1;
            float c2 = (acc[mt][nt][2] - mu1) * rs1 * g0 + l0;
            float c3 = (acc[mt][nt][3] - mu1) * rs1 * g1 + l1;
            *(__half2*)(Ch + (size_t)gr * Nn + col)       = __floats2half2_rn(c0, c1);
            *(__half2*)(Ch + (size_t)(gr + 8) * Nn + col) = __floats2half2_rn(c2, c3);
        }
    }
}

// ================= small-tile fp16 GEMM (slot path): 128x64, BK=32 ===========
// EPI 10: +bias -> fp32 (dual-source via blockIdx.z).
// EPI 11: relu(+bias) -> fp16.  EPI 12: +bias +res -> fp32 Cf AND fp16 Ch.
#define HROW 40
#define STG64_BYTES ((128 + 64) * HROW * 2)
#define H64_DSMEM (3 * STG64_BYTES)

template<int EPI>
__global__ void __launch_bounds__(256, 3)
hgemm64_kernel(const __half* __restrict__ A0, const __half* __restrict__ B0,
               int Nn, int K, float* __restrict__ Cf0, __half* __restrict__ Ch,
               const float* __restrict__ bias0, const float* __restrict__ res,
               const __half* A1, const __half* B1,
               float* Cf1, const float* bias1) {
    extern __shared__ __align__(16) __half smh[];
    uint32_t smb;
    asm("{ .reg .u64 t; cvta.to.shared.u64 t, %1; cvt.u32.u64 %0, t; }"
        : "=r"(smb) : "l"(smh));

    const __half* A = A0;
    const __half* Bw = B0;
    float* Cf = Cf0;
    const float* bias = bias0;
    if (EPI == 10 && blockIdx.z == 1) { A = A1; Bw = B1; Cf = Cf1; bias = bias1; }

    int tid = threadIdx.x;
    int lane = tid & 31;
    int warp = tid >> 5;
    int grp = lane >> 2, tig = lane & 3;
    int wm = (warp & 3) * 32;
    int wn = (warp >> 2) * 32;
    int bm = blockIdx.y * 128;
    int bn = blockIdx.x * 64;

    const __half* Abm = A + (size_t)bm * K;
    const __half* Bbn = Bw + (size_t)bn * K;

    float acc[2][4][4];
    #pragma unroll
    for (int mt = 0; mt < 2; mt++)
        #pragma unroll
        for (int nt = 0; nt < 4; nt++)
            #pragma unroll
            for (int i = 0; i < 4; i++) acc[mt][nt][i] = 0.f;

    int nit = K / 32;
    #pragma unroll
    for (int s = 0; s < 2; s++) {
        uint32_t base = smb + s * STG64_BYTES;
        #pragma unroll
        for (int j = 0; j < 2; j++) {
            int e = tid + j * 256;
            int r = e >> 2, c = e & 3;
            CP_ASYNC16(base + (r * HROW + c * 8) * 2, Abm + (size_t)r * K + s * 32 + c * 8);
        }
        {
            int r = tid >> 2, c = tid & 3;
            CP_ASYNC16(base + (128 * HROW + r * HROW + c * 8) * 2,
                       Bbn + (size_t)r * K + s * 32 + c * 8);
        }
        CP_COMMIT();
    }

    for (int it = 0; it < nit; it++) {
        CP_WAIT1();
        __syncthreads();
        uint32_t sa = smb + (it % 3) * STG64_BYTES;
        uint32_t sb = sa + 128 * HROW * 2;
        if (it + 2 < nit) {
            uint32_t base = smb + ((it + 2) % 3) * STG64_BYTES;
            #pragma unroll
            for (int j = 0; j < 2; j++) {
                int e = tid + j * 256;
                int r = e >> 2, c = e & 3;
                CP_ASYNC16(base + (r * HROW + c * 8) * 2,
                           Abm + (size_t)r * K + (it + 2) * 32 + c * 8);
            }
            {
                int r = tid >> 2, c = tid & 3;
                CP_ASYNC16(base + (128 * HROW + r * HROW + c * 8) * 2,
                           Bbn + (size_t)r * K + (it + 2) * 32 + c * 8);
            }
        }
        CP_COMMIT();

        #pragma unroll
        for (int kc = 0; kc < 2; kc++) {
            uint32_t afr[2][4], bfr[4][2];
            #pragma unroll
            for (int mt = 0; mt < 2; mt++) {
                uint32_t addr = sa + ((wm + mt * 16 + (lane & 15)) * HROW
                                      + kc * 16 + (lane >> 4) * 8) * 2;
                ldmx4(afr[mt][0], afr[mt][1], afr[mt][2], afr[mt][3], addr);
            }
            #pragma unroll
            for (int ng = 0; ng < 2; ng++) {
                uint32_t r0, r1, r2, r3;
                uint32_t addr = sb + ((wn + ng * 16 + (lane & 15)) * HROW
                                      + kc * 16 + (lane >> 4) * 8) * 2;
                ldmx4(r0, r1, r2, r3, addr);
                bfr[2 * ng][0] = r0; bfr[2 * ng + 1][0] = r1;
                bfr[2 * ng][1] = r2; bfr[2 * ng + 1][1] = r3;
            }
            #pragma unroll
            for (int mt = 0; mt < 2; mt++)
                #pragma unroll
                for (int nt = 0; nt < 4; nt++)
                    mma_f16(acc[mt][nt], afr[mt], bfr[nt]);
        }
    }

    #pragma unroll
    for (int mt = 0; mt < 2; mt++) {
        int r0 = bm + wm + mt * 16 + grp;
        #pragma unroll
        for (int nt = 0; nt < 4; nt++) {
            int col = bn + wn + nt * 8 + tig * 2;
            float b0 = __ldg(&bias[col]), b1 = __ldg(&bias[col + 1]);
            float c0 = acc[mt][nt][0] + b0, c1 = acc[mt][nt][1] + b1;
            float c2 = acc[mt][nt][2] + b0, c3 = acc[mt][nt][3] + b1;
            if (EPI == 10) {
                *(float2*)(Cf + (size_t)r0 * Nn + col)       = make_float2(c0, c1);
                *(float2*)(Cf + (size_t)(r0 + 8) * Nn + col) = make_float2(c2, c3);
            } else if (EPI == 11) {
                c0 = fmaxf(c0, 0.f); c1 = fmaxf(c1, 0.f);
                c2 = fmaxf(c2, 0.f); c3 = fmaxf(c3, 0.f);
                *(__half2*)(Ch + (size_t)r0 * Nn + col)       = __floats2half2_rn(c0, c1);
                *(__half2*)(Ch + (size_t)(r0 + 8) * Nn + col) = __floats2half2_rn(c2, c3);
            } else {   // EPI 12: residual + dual store
                float2 ra = *(const float2*)(res + (size_t)r0 * Nn + col);
                float2 rb = *(const float2*)(res + (size_t)(r0 + 8) * Nn + col);
                c0 += ra.x; c1 += ra.y; c2 += rb.x; c3 += rb.y;
                *(float2*)(Cf + (size_t)r0 * Nn + col)       = make_float2(c0, c1);
                *(float2*)(Cf + (size_t)(r0 + 8) * Nn + col) = make_float2(c2, c3);
                *(__half2*)(Ch + (size_t)r0 * Nn + col)       = __floats2half2_rn(c0, c1);
                *(__half2*)(Ch + (size_t)(r0 + 8) * Nn + col) = __floats2half2_rn(c2, c3);
            }
        }
    }
}

// ================= prep / small kernels =================
__global__ void ln_stats_f2h_kernel(const float* __restrict__ x, __half* __restrict__ xh) {
    int row = blockIdx.x * 8 + (threadIdx.x >> 5);
    int lane = threadIdx.x & 31;
    const float* p = x + (size_t)row * FDIN;
    __half* ph = xh + (size_t)row * FDIN;
    float v[24];
    float s = 0.f, ss = 0.f;
    #pragma unroll
    for (int k = 0; k < 24; k++) {
        v[k] = p[lane + 32 * k];
        s += v[k];
        ss += v[k] * v[k];
    }
    #pragma unroll
    for (int k = 0; k < 24; k++) ph[lane + 32 * k] = __float2half(v[k]);
    #pragma unroll
    for (int o = 16; o; o >>= 1) {
        s  += __shfl_xor_sync(0xffffffffu, s, o);
        ss += __shfl_xor_sync(0xffffffffu, ss, o);
    }
    float m = s * (1.f / FDIN);
    float var = ss * (1.f / FDIN) - m * m;
    if (lane == 0) { g_mean[row] = m; g_rstd[row] = rsqrtf(var + 1e-5f); }
}

// dual f2h: blockIdx.x < half -> (in0,out0); else (in1,out1)
__global__ void conv2_f2h_kernel(const float* __restrict__ in0, __half* __restrict__ out0,
                                 const float* __restrict__ in1, __half* __restrict__ out1,
                                 int halfBlocks) {
    const float* in = in0;
    __half* out = out0;
    int bx = blockIdx.x;
    if (bx >= halfBlocks) { in = in1; out = out1; bx -= halfBlocks; }
    size_t i = ((size_t)bx * 256 + threadIdx.x) * 4;
    float4 v = *(const float4*)(in + i);
    *(__half2*)(out + i)     = __floats2half2_rn(v.x, v.y);
    *(__half2*)(out + i + 2) = __floats2half2_rn(v.z, v.w);
}

__global__ void trans_h_kernel(const float* __restrict__ in, __half* __restrict__ out,
                               int R, int C, const float* __restrict__ scale) {
    __shared__ float t[32][33];
    int bx = blockIdx.x * 32, by = blockIdx.y * 32;
    int x = bx + threadIdx.x;
    #pragma unroll
    for (int j = 0; j < 32; j += 8) {
        int y = by + threadIdx.y + j;
        float s = scale ? scale[y] : 1.f;
        t[threadIdx.y + j][threadIdx.x] = in[(size_t)y * C + x] * s;
    }
    __syncthreads();
    int x2 = by + threadIdx.x;
    #pragma unroll
    for (int j = 0; j < 32; j += 8) {
        int y2 = bx + threadIdx.y + j;
        out[(size_t)y2 * R + x2] = __float2half(t[threadIdx.x][threadIdx.y + j]);
    }
}

__global__ void trans_f_kernel(const float* __restrict__ in, float* __restrict__ out,
                               int R, int C) {
    __shared__ float t[32][33];
    int bx = blockIdx.x * 32, by = blockIdx.y * 32;
    int x = bx + threadIdx.x;
    #pragma unroll
    for (int j = 0; j < 32; j += 8)
        t[threadIdx.y + j][threadIdx.x] = in[(size_t)(by + threadIdx.y + j) * C + x];
    __syncthreads();
    int x2 = by + threadIdx.x;
    #pragma unroll
    for (int j = 0; j < 32; j += 8)
        out[(size_t)(bx + threadIdx.y + j) * R + x2] = t[threadIdx.x][threadIdx.y + j];
}

__global__ void wkv_h_kernel(const float* __restrict__ wk, const float* __restrict__ wv) {
    int i = blockIdx.x * 256 + threadIdx.x;
    g_wkvh[i] = __float2half(wk[i]);
    g_wkvh[DD * DD + i] = __float2half(wv[i]);
}

// coalesced prep_sums: grid (FDIN/256, 8); k-split with atomics (gB/bBp pre-zeroed)
__global__ void prep_sums_kernel(const float* __restrict__ w1,
                                 const float* __restrict__ g,
                                 const float* __restrict__ b,
                                 const float* __restrict__ b1) {
    int n = blockIdx.x * 256 + threadIdx.x;
    int k0 = blockIdx.y * 96;
    float s1 = 0.f, s2 = 0.f;
    #pragma unroll 8
    for (int k = k0; k < k0 + 96; k++) {
        float w = w1[(size_t)k * FDIN + n];
        s1 += g[k] * w;
        s2 += b[k] * w;
    }
    if (blockIdx.y == 0) s2 += b1[n];
    atomicAdd(&g_gB[n], s1);
    atomicAdd(&g_bBp[n], s2);
}

__global__ void slots_init_kernel(const float* __restrict__ si) {
    int i = blockIdx.x * 256 + threadIdx.x;
    float v = si[i & (NS * DD - 1)];
    g_slots[i] = v;
    g_slotsh[i] = __float2half(v);
}

__device__ __forceinline__ float2 block_meanvar_256(float v, float* r1, float* r2) {
    float s = v, q = v * v;
    #pragma unroll
    for (int o = 16; o; o >>= 1) {
        s += __shfl_xor_sync(0xffffffffu, s, o);
        q += __shfl_xor_sync(0xffffffffu, q, o);
    }
    int w = threadIdx.x >> 5, lane = threadIdx.x & 31;
    if (lane == 0) { r1[w] = s; r2[w] = q; }
    __syncthreads();
    float sum = 0.f, sq = 0.f;
    #pragma unroll
    for (int i = 0; i < 8; i++) { sum += r1[i]; sq += r2[i]; }
    __syncthreads();
    float m = sum * (1.f / 256.f);
    float var = sq * (1.f / 256.f) - m * m;
    return make_float2(m, rsqrtf(var + 1e-5f));
}

__global__ void qproj_kernel(const float* __restrict__ ng, const float* __restrict__ nb) {
    __shared__ float sln[DD];
    __shared__ float r1[8], r2[8];
    int row = blockIdx.x, tid = threadIdx.x;
    float v = g_slots[row * DD + tid];
    float2 mv = block_meanvar_256(v, r1, r2);
    sln[tid] = (v - mv.x) * mv.y * ng[tid] + nb[tid];
    g_U[row * DD + tid] = 0.f;
    if (tid == 0) g_rowsum[row] = 0.f;
    __syncthreads();
    float acc = 0.f;
    #pragma unroll 8
    for (int d = 0; d < DD; d++) acc += sln[d] * g_wqT[d * DD + tid];
    g_q[row * DD + tid] = acc;
}

__global__ void __launch_bounds__(256)
attn_kernel() {
    int b = blockIdx.x, ch = blockIdx.y;
    int warp = threadIdx.x >> 5, lane = threadIdx.x & 31;
    __shared__ float qs[NS * DD];
    __shared__ float dots[8][NS];
    __shared__ float aw[8][NS];
    for (int i = threadIdx.x; i < NS * DD; i += 256) qs[i] = g_q[b * NS * DD + i];
    __syncthreads();
    float qreg[8];
    #pragma unroll
    for (int k = 0; k < 4; k++) {
        qreg[2 * k]     = qs[warp * DD + 2 * (lane + 32 * k)];
        qreg[2 * k + 1] = qs[warp * DD + 2 * (lane + 32 * k) + 1];
    }
    float2 uacc[4];
    #pragma unroll
    for (int k = 0; k < 4; k++) uacc[k] = make_float2(0.f, 0.f);
    float rsum = 0.f;
    const float scale = 0.0625f;
    int t0 = ch * 256;
    const __half* kvb = g_kvh + ((size_t)b * NTOK + t0) * 512;

    for (int tt = 0; tt < 256; tt += 8) {
        #pragma unroll
        for (int u = 0; u < 8; u++) {
            const __half2* kp = (const __half2*)(kvb + (size_t)(tt + u) * 512);
            float d = 0.f;
            #pragma unroll
            for (int k = 0; k < 4; k++) {
                float2 kv2 = __half22float2(kp[lane + 32 * k]);
                d += qreg[2 * k] * kv2.x + qreg[2 * k + 1] * kv2.y;
            }
            #pragma unroll
            for (int o = 16; o; o >>= 1) d += __shfl_xor_sync(0xffffffffu, d, o);
            if (lane == 0) dots[u][warp] = d * scale;
        }
        __syncthreads();
        if (threadIdx.x < 64) {
            int u = threadIdx.x >> 3, s = threadIdx.x & 7;
            float mx = -1e30f;
            #pragma unroll
            for (int s2 = 0; s2 < NS; s2++) mx = fmaxf(mx, dots[u][s2]);
            float e = expf(dots[u][s] - mx);
            float sum = e;
            #pragma unroll
            for (int o = 1; o < 8; o <<= 1) sum += __shfl_xor_sync(0xffffffffu, sum, o);
            aw[u][s] = e / sum + 1e-8f;
        }
        __syncthreads();
        #pragma unroll
        for (int u = 0; u < 8; u++) {
            float a = aw[u][warp];
            const __half2* vp = (const __half2*)(kvb + (size_t)(tt + u) * 512 + 256);
            #pragma unroll
            for (int k = 0; k < 4; k++) {
                float2 vv = __half22float2(vp[lane + 32 * k]);
                uacc[k].x += a * vv.x;
                uacc[k].y += a * vv.y;
            }
            rsum += a;
        }
        __syncthreads();
    }
    float* up = g_U + (b * NS + warp) * DD;
    #pragma unroll
    for (int k = 0; k < 4; k++) {
        atomicAdd(&up[2 * (lane + 32 * k)], uacc[k].x);
        atomicAdd(&up[2 * (lane + 32 * k) + 1], uacc[k].y);
    }
    if (lane == 0) atomicAdd(&g_rowsum[b * NS + warp], rsum);
}

__global__ void updfin_kernel() {
    int i = blockIdx.x * 256 + threadIdx.x;
    g_updh[i] = __float2half(g_U[i] / g_rowsum[i >> 8]);
}

__global__ void gru_pw_kernel(const float* __restrict__ mlng,
                              const float* __restrict__ mlnb) {
    __shared__ float r1[8], r2[8];
    int row = blockIdx.x, tid = threadIdx.x;
    const float* gi = g_gi + row * 3 * DD;
    const float* gh = g_gh + row * 3 * DD;
    float ir = gi[tid], iz = gi[tid + 256], inn = gi[tid + 512];
    float hr = gh[tid], hz = gh[tid + 256], hn = gh[tid + 512];
    float sprev = g_slots[row * DD + tid];
    float r = 1.f / (1.f + expf(-(ir + hr)));
    float z = 1.f / (1.f + expf(-(iz + hz)));
    float n = tanhf(inn + r * hn);
    float h = (1.f - z) * n + z * sprev;
    g_hbuf[row * DD + tid] = h;
    float2 mv = block_meanvar_256(h, r1, r2);
    g_mlpinh[row * DD + tid] = __float2half((h - mv.x) * mv.y * mlng[tid] + mlnb[tid]);
}

// ================= launch =================
extern "C" void kernel_launch(void* const* d_in, const int* in_sizes, int n_in,
                              void* d_out, int out_size) {
    const float* inputs   = (const float*)d_in[0];
    const float* slots_in = (const float*)d_in[1];
    const float* ln1g = (const float*)d_in[2];
    const float* ln1b = (const float*)d_in[3];
    const float* w1   = (const float*)d_in[4];
    const float* b1   = (const float*)d_in[5];
    const float* w2   = (const float*)d_in[6];
    const float* b2   = (const float*)d_in[7];
    const float* ln2g = (const float*)d_in[8];
    const float* ln2b = (const float*)d_in[9];
    const float* wq   = (const float*)d_in[10];
    const float* wk   = (const float*)d_in[11];
    const float* wv   = (const float*)d_in[12];
    const float* normg = (const float*)d_in[13];
    const float* normb = (const float*)d_in[14];
    const float* gwih = (const float*)d_in[15];
    const float* gwhh = (const float*)d_in[16];
    const float* gbih = (const float*)d_in[17];
    const float* gbhh = (const float*)d_in[18];
    const float* mlng = (const float*)d_in[19];
    const float* mlnb = (const float*)d_in[20];
    const float* mw1  = (const float*)d_in[21];
    const float* mb1  = (const float*)d_in[22];
    const float* mw2  = (const float*)d_in[23];
    const float* mb2  = (const float*)d_in[24];
    float* out = (float*)d_out;

    __half *p_inh, *p_h1h, *p_featsh, *p_kvh, *p_w1h, *p_w2h, *p_wkvh;
    __half *p_wihh, *p_whhh, *p_mw1h, *p_mw2h, *p_updh, *p_mlpinh, *p_hhh, *p_slotsh;
    float *p_wqT, *p_slots, *p_gi, *p_gh, *p_hbuf, *p_gB, *p_bBp;
    cudaGetSymbolAddress((void**)&p_inh,    g_inh);
    cudaGetSymbolAddress((void**)&p_h1h,    g_h1h);
    cudaGetSymbolAddress((void**)&p_featsh, g_featsh);
    cudaGetSymbolAddress((void**)&p_kvh,    g_kvh);
    cudaGetSymbolAddress((void**)&p_w1h,    g_w1h);
    cudaGetSymbolAddress((void**)&p_w2h,    g_w2h);
    cudaGetSymbolAddress((void**)&p_wkvh,   g_wkvh);
    cudaGetSymbolAddress((void**)&p_wihh,   g_wihh);
    cudaGetSymbolAddress((void**)&p_whhh,   g_whhh);
    cudaGetSymbolAddress((void**)&p_mw1h,   g_mw1h);
    cudaGetSymbolAddress((void**)&p_mw2h,   g_mw2h);
    cudaGetSymbolAddress((void**)&p_updh,   g_updh);
    cudaGetSymbolAddress((void**)&p_mlpinh, g_mlpinh);
    cudaGetSymbolAddress((void**)&p_hhh,    g_hhh);
    cudaGetSymbolAddress((void**)&p_slotsh, g_slotsh);
    cudaGetSymbolAddress((void**)&p_wqT,    g_wqT);
    cudaGetSymbolAddress((void**)&p_slots,  g_slots);
    cudaGetSymbolAddress((void**)&p_gi,     g_gi);
    cudaGetSymbolAddress((void**)&p_gh,     g_gh);
    cudaGetSymbolAddress((void**)&p_hbuf,   g_hbuf);
    cudaGetSymbolAddress((void**)&p_gB,     g_gB);
    cudaGetSymbolAddress((void**)&p_bBp,    g_bBp);

    // smem opt-ins (above 48 KB default)
    cudaFuncSetAttribute(hgemm128_kernel<1>, cudaFuncAttributeMaxDynamicSharedMemorySize, H128_DSMEM);
    cudaFuncSetAttribute(hgemm128_kernel<3>, cudaFuncAttributeMaxDynamicSharedMemorySize, H128_DSMEM);
    cudaFuncSetAttribute(hgemm2ln_kernel,    cudaFuncAttributeMaxDynamicSharedMemorySize, H256_DSMEM);

    dim3 tb(32, 8);
    cudaMemsetAsync(p_gB, 0, FDIN * sizeof(float));
    cudaMemsetAsync(p_bBp, 0, FDIN * sizeof(float));
    // 0: fused LN stats + fp16 conversion of inputs
    ln_stats_f2h_kernel<<<MROWS / 8, 256>>>(inputs, p_inh);
    // 1: w1 -> [N][K] fp16 scaled by ln1g
    trans_h_kernel<<<dim3(FDIN / 32, FDIN / 32), tb>>>(w1, p_w1h, FDIN, FDIN, ln1g);
    // 2: epilogue fold vectors
    prep_sums_kernel<<<dim3(FDIN / 256, 8), 256>>>(w1, ln1g, ln1b, b1);
    // 3: GEMM1 (128x128, BK=64)   << ncu window
    hgemm128_kernel<1><<<dim3(FDIN / 128, MROWS / 128), 256, H128_DSMEM>>>(
        p_inh, p_w1h, FDIN, FDIN, p_h1h);
    // 4: w2 -> [N][K] fp16
    trans_h_kernel<<<dim3(DD / 32, FDIN / 32), tb>>>(w2, p_w2h, FDIN, DD, nullptr);
    // 5: GEMM2 fused row-LN: feats = LN(h1 @ w2 + b2) -> fp16
    hgemm2ln_kernel<<<dim3(1, MROWS / 128), 512, H256_DSMEM>>>(
        p_h1h, p_w2h, FDIN, p_featsh, b2, ln2g, ln2b);
    // 6: wk|wv -> fp16
    wkv_h_kernel<<<DD * DD / 256, 256>>>(wk, wv);
    // 7: KV GEMM -> fp16
    hgemm128_kernel<3><<<dim3(2 * DD / 128, MROWS / 128), 256, H128_DSMEM>>>(
        p_featsh, p_wkvh, 2 * DD, DD, p_kvh);

    // slot-path weight prep
    trans_f_kernel<<<dim3(DD / 32, DD / 32), tb>>>(wq, p_wqT, DD, DD);
    conv2_f2h_kernel<<<2 * (3 * DD * DD / 1024), 256>>>(gwih, p_wihh, gwhh, p_whhh,
                                                        3 * DD * DD / 1024);
    trans_h_kernel<<<dim3(4 * DD / 32, DD / 32), tb>>>(mw1, p_mw1h, DD, 4 * DD, nullptr);
    trans_h_kernel<<<dim3(DD / 32, 4 * DD / 32), tb>>>(mw2, p_mw2h, 4 * DD, DD, nullptr);
    slots_init_kernel<<<SROWS * DD / 256, 256>>>(slots_in);

    for (int t = 0; t < ITERS; t++) {
        qproj_kernel<<<SROWS, 256>>>(normg, normb);
        attn_kernel<<<dim3(BNUM, 16), 256>>>();
        updfin_kernel<<<SROWS, 256>>>();
        // gi and gh in ONE launch (z=0: updh@wih^T+bih -> gi; z=1: slotsh@whh^T+bhh -> gh)
        hgemm64_kernel<10><<<dim3(3 * DD / 64, SROWS / 128, 2), 256, H64_DSMEM>>>(
            p_updh, p_wihh, 3 * DD, DD, p_gi, nullptr, gbih, nullptr,
            p_slotsh, p_whhh, p_gh, gbhh);
        gru_pw_kernel<<<SROWS, 256>>>(mlng, mlnb);
        hgemm64_kernel<11><<<dim3(4 * DD / 64, SROWS / 128), 256, H64_DSMEM>>>(
            p_mlpinh, p_mw1h, 4 * DD, DD, nullptr, p_hhh, mb1, nullptr,
            nullptr, nullptr, nullptr, nullptr);
        float* dst = (t == ITERS - 1) ? out : p_slots;
        hgemm64_kernel<12><<<dim3(DD / 64, SROWS / 128), 256, H64_DSMEM>>>(
            p_hhh, p_mw2h, DD, 4 * DD, dst, p_slotsh, mb2, p_hbuf,
            nullptr, nullptr, nullptr, nullptr);
    }
}

// round 15
// speedup vs baseline: 1.1679x; 1.1244x over previous
#include <cuda_runtime.h>
#include <cuda_fp16.h>
#include <math.h>
#include <stdint.h>

#define BNUM 32
#define NTOK 4096
#define FDIN 768
#define DD 256
#define NS 8
#define MROWS (BNUM * NTOK)   // 131072
#define SROWS (BNUM * NS)     // 768 slot rows
#define ITERS 3

// ---------------- scratch (static __device__ — no allocation) ----------------
__device__ float  g_mean[MROWS];
__device__ float  g_rstd[MROWS];
__device__ __half g_inh[(size_t)MROWS * FDIN];
__device__ __half g_h1h[(size_t)MROWS * FDIN];
__device__ __half g_featsh[(size_t)MROWS * DD];
__device__ __half g_kvh[(size_t)MROWS * 2 * DD];  // [row][512]: keys | vals fp16
__device__ __half g_w1h[FDIN * FDIN];             // [N=768][K=768], scaled by ln1g
__device__ float  g_gB[FDIN];
__device__ float  g_bBp[FDIN];
__device__ __half g_w2h[DD * FDIN];               // [N=256][K=768]
__device__ __half g_wkvh[2 * DD * DD];            // [N=512][K=256]
__device__ float  g_wqT[DD * DD];
// GRU / MLP weights fp16 (K-major)
__device__ __half g_wihh[3 * DD * DD];
__device__ __half g_whhh[3 * DD * DD];
__device__ __half g_mw1h[4 * DD * DD];
__device__ __half g_mw2h[DD * 4 * DD];
// iteration state
__device__ float  g_slots[SROWS * DD];
__device__ __half g_slotsh[SROWS * DD];
__device__ float  g_q[SROWS * DD];
__device__ float  g_U[SROWS * DD];
__device__ float  g_rowsum[SROWS];
__device__ __half g_updh[SROWS * DD];
__device__ float  g_gi[SROWS * 3 * DD];
__device__ float  g_gh[SROWS * 3 * DD];
__device__ float  g_hbuf[SROWS * DD];
__device__ __half g_mlpinh[SROWS * DD];
__device__ __half g_hhh[SROWS * 4 * DD];

// ================= asm helpers =================
#define CP_ASYNC16(dst, src) \
    asm volatile("cp.async.cg.shared.global [%0], [%1], 16;\n" :: "r"(dst), "l"(src))
#define CP_COMMIT() asm volatile("cp.async.commit_group;\n" ::: "memory")
#define CP_WAIT1()  asm volatile("cp.async.wait_group 1;\n" ::: "memory")

__device__ __forceinline__ void ldmx4(uint32_t& r0, uint32_t& r1, uint32_t& r2,
                                      uint32_t& r3, uint32_t addr) {
    asm volatile("ldmatrix.sync.aligned.m8n8.x4.shared.b16 {%0,%1,%2,%3}, [%4];"
                 : "=r"(r0), "=r"(r1), "=r"(r2), "=r"(r3) : "r"(addr));
}

__device__ __forceinline__ void mma_f16(float* c, const uint32_t* a, const uint32_t* b) {
    asm volatile(
        "mma.sync.aligned.m16n8k16.row.col.f32.f16.f16.f32 "
        "{%0,%1,%2,%3}, {%4,%5,%6,%7}, {%8,%9}, {%0,%1,%2,%3};"
        : "+f"(c[0]), "+f"(c[1]), "+f"(c[2]), "+f"(c[3])
        : "r"(a[0]), "r"(a[1]), "r"(a[2]), "r"(a[3]), "r"(b[0]), "r"(b[1]));
}

// packed f32x2 (sm_100+ base feature; doubles fp32 FMA throughput)
__device__ __forceinline__ unsigned long long pk2(float x, float y) {
    unsigned long long r;
    asm("mov.b64 %0, {%1, %2};" : "=l"(r) : "f"(x), "f"(y));
    return r;
}
__device__ __forceinline__ float2 upk2(unsigned long long v) {
    float2 f;
    asm("mov.b64 {%0, %1}, %2;" : "=f"(f.x), "=f"(f.y) : "l"(v));
    return f;
}
#define FMA2(acc, a, b) \
    asm("fma.rn.f32x2 %0, %1, %2, %0;" : "+l"(acc) : "l"(a), "l"(b))

// ================= big-tile fp16 GEMM (GEMM1/KV): 128x128, BK=64 ============
// EPI 1: LN-fold+relu -> fp16. EPI 3: raw -> fp16.
#define HR128 72
#define STG128_BYTES (256 * HR128 * 2)    // 36864
#define H128_DSMEM (3 * STG128_BYTES)     // 110592

template<int EPI>
__global__ void __launch_bounds__(256)
hgemm128_kernel(const __half* __restrict__ A, const __half* __restrict__ Bw,
                int Nn, int K, __half* __restrict__ Ch) {
    extern __shared__ __align__(16) __half smh[];
    uint32_t smb;
    asm("{ .reg .u64 t; cvta.to.shared.u64 t, %1; cvt.u32.u64 %0, t; }"
        : "=r"(smb) : "l"(smh));

    int tid = threadIdx.x;
    int lane = tid & 31;
    int warp = tid >> 5;
    int grp = lane >> 2, tig = lane & 3;
    int wm = (warp & 3) * 32;
    int wn = (warp >> 2) * 64;
    int bm = blockIdx.y * 128;
    int bn = blockIdx.x * 128;

    const __half* Abm = A + (size_t)bm * K;
    const __half* Bbn = Bw + (size_t)bn * K;

    float acc[2][8][4];
    #pragma unroll
    for (int mt = 0; mt < 2; mt++)
        #pragma unroll
        for (int nt = 0; nt < 8; nt++)
            #pragma unroll
            for (int i = 0; i < 4; i++) acc[mt][nt][i] = 0.f;

    int nit = K / 64;
    #pragma unroll
    for (int s = 0; s < 2; s++) {
        uint32_t base = smb + s * STG128_BYTES;
        #pragma unroll
        for (int j = 0; j < 4; j++) {
            int e = tid + j * 256;
            int r = e >> 3, c = e & 7;
            CP_ASYNC16(base + (r * HR128 + c * 8) * 2,
                       Abm + (size_t)r * K + s * 64 + c * 8);
            CP_ASYNC16(base + (128 * HR128 + r * HR128 + c * 8) * 2,
                       Bbn + (size_t)r * K + s * 64 + c * 8);
        }
        CP_COMMIT();
    }

    for (int it = 0; it < nit; it++) {
        CP_WAIT1();
        __syncthreads();
        uint32_t sa = smb + (it % 3) * STG128_BYTES;
        uint32_t sb = sa + 128 * HR128 * 2;
        if (it + 2 < nit) {
            uint32_t base = smb + ((it + 2) % 3) * STG128_BYTES;
            #pragma unroll
            for (int j = 0; j < 4; j++) {
                int e = tid + j * 256;
                int r = e >> 3, c = e & 7;
                CP_ASYNC16(base + (r * HR128 + c * 8) * 2,
                           Abm + (size_t)r * K + (it + 2) * 64 + c * 8);
                CP_ASYNC16(base + (128 * HR128 + r * HR128 + c * 8) * 2,
                           Bbn + (size_t)r * K + (it + 2) * 64 + c * 8);
            }
        }
        CP_COMMIT();

        #pragma unroll
        for (int kc = 0; kc < 4; kc++) {
            uint32_t afr[2][4], bfr[8][2];
            #pragma unroll
            for (int mt = 0; mt < 2; mt++) {
                uint32_t addr = sa + ((wm + mt * 16 + (lane & 15)) * HR128
                                      + kc * 16 + (lane >> 4) * 8) * 2;
                ldmx4(afr[mt][0], afr[mt][1], afr[mt][2], afr[mt][3], addr);
            }
            #pragma unroll
            for (int ng = 0; ng < 4; ng++) {
                uint32_t r0, r1, r2, r3;
                uint32_t addr = sb + ((wn + ng * 16 + (lane & 15)) * HR128
                                      + kc * 16 + (lane >> 4) * 8) * 2;
                ldmx4(r0, r1, r2, r3, addr);
                bfr[2 * ng][0] = r0; bfr[2 * ng + 1][0] = r1;
                bfr[2 * ng][1] = r2; bfr[2 * ng + 1][1] = r3;
            }
            #pragma unroll
            for (int mt = 0; mt < 2; mt++)
                #pragma unroll
                for (int nt = 0; nt < 8; nt++)
                    mma_f16(acc[mt][nt], afr[mt], bfr[nt]);
        }
    }

    #pragma unroll
    for (int mt = 0; mt < 2; mt++) {
        int r0 = bm + wm + mt * 16 + grp;
        float mu0 = 0.f, rs0 = 0.f, mu1 = 0.f, rs1 = 0.f;
        if (EPI == 1) {
            mu0 = g_mean[r0]; rs0 = g_rstd[r0];
            mu1 = g_mean[r0 + 8]; rs1 = g_rstd[r0 + 8];
        }
        #pragma unroll
        for (int nt = 0; nt < 8; nt++) {
            int col = bn + wn + nt * 8 + tig * 2;
            float c0 = acc[mt][nt][0], c1 = acc[mt][nt][1];
            float c2 = acc[mt][nt][2], c3 = acc[mt][nt][3];
            if (EPI == 1) {
                float gb0 = __ldg(&g_gB[col]), gb1 = __ldg(&g_gB[col + 1]);
                float bb0 = __ldg(&g_bBp[col]), bb1 = __ldg(&g_bBp[col + 1]);
                c0 = fmaxf(c0 * rs0 - mu0 * rs0 * gb0 + bb0, 0.f);
                c1 = fmaxf(c1 * rs0 - mu0 * rs0 * gb1 + bb1, 0.f);
                c2 = fmaxf(c2 * rs1 - mu1 * rs1 * gb0 + bb0, 0.f);
                c3 = fmaxf(c3 * rs1 - mu1 * rs1 * gb1 + bb1, 0.f);
            }
            *(__half2*)(Ch + (size_t)r0 * Nn + col)       = __floats2half2_rn(c0, c1);
            *(__half2*)(Ch + (size_t)(r0 + 8) * Nn + col) = __floats2half2_rn(c2, c3);
        }
    }
}

// ========== GEMM2 fused row-LN: 128x256 tile, 512 threads, BK=64 ============
#define STG256_BYTES ((128 + 256) * HR128 * 2)   // 55296
#define H256_DSMEM (3 * STG256_BYTES)            // 165888

__global__ void __launch_bounds__(512)
hgemm2ln_kernel(const __half* __restrict__ A, const __half* __restrict__ Bw,
                int K, __half* __restrict__ Ch,
                const float* __restrict__ bias,
                const float* __restrict__ lng, const float* __restrict__ lnb) {
    extern __shared__ __align__(16) __half smh[];
    uint32_t smb;
    asm("{ .reg .u64 t; cvta.to.shared.u64 t, %1; cvt.u32.u64 %0, t; }"
        : "=r"(smb) : "l"(smh));

    const int Nn = 256;
    int tid = threadIdx.x;
    int lane = tid & 31;
    int warp = tid >> 5;
    int grp = lane >> 2, tig = lane & 3;
    int wm = (warp & 3) * 32;
    int wn = (warp >> 2) * 64;
    int bm = blockIdx.y * 128;

    const __half* Abm = A + (size_t)bm * K;
    const __half* Bbn = Bw;

    float acc[2][8][4];
    #pragma unroll
    for (int mt = 0; mt < 2; mt++)
        #pragma unroll
        for (int nt = 0; nt < 8; nt++)
            #pragma unroll
            for (int i = 0; i < 4; i++) acc[mt][nt][i] = 0.f;

    int nit = K / 64;
    #pragma unroll
    for (int s = 0; s < 2; s++) {
        uint32_t base = smb + s * STG256_BYTES;
        #pragma unroll
        for (int j = 0; j < 2; j++) {
            int e = tid + j * 512;
            int r = e >> 3, c = e & 7;
            CP_ASYNC16(base + (r * HR128 + c * 8) * 2,
                       Abm + (size_t)r * K + s * 64 + c * 8);
        }
        #pragma unroll
        for (int j = 0; j < 4; j++) {
            int e = tid + j * 512;
            int r = e >> 3, c = e & 7;
            CP_ASYNC16(base + (128 * HR128 + r * HR128 + c * 8) * 2,
                       Bbn + (size_t)r * K + s * 64 + c * 8);
        }
        CP_COMMIT();
    }

    for (int it = 0; it < nit; it++) {
        CP_WAIT1();
        __syncthreads();
        uint32_t sa = smb + (it % 3) * STG256_BYTES;
        uint32_t sb = sa + 128 * HR128 * 2;
        if (it + 2 < nit) {
            uint32_t base = smb + ((it + 2) % 3) * STG256_BYTES;
            #pragma unroll
            for (int j = 0; j < 2; j++) {
                int e = tid + j * 512;
                int r = e >> 3, c = e & 7;
                CP_ASYNC16(base + (r * HR128 + c * 8) * 2,
                           Abm + (size_t)r * K + (it + 2) * 64 + c * 8);
            }
            #pragma unroll
            for (int j = 0; j < 4; j++) {
                int e = tid + j * 512;
                int r = e >> 3, c = e & 7;
                CP_ASYNC16(base + (128 * HR128 + r * HR128 + c * 8) * 2,
                           Bbn + (size_t)r * K + (it + 2) * 64 + c * 8);
            }
        }
        CP_COMMIT();

        #pragma unroll
        for (int kc = 0; kc < 4; kc++) {
            uint32_t afr[2][4], bfr[8][2];
            #pragma unroll
            for (int mt = 0; mt < 2; mt++) {
                uint32_t addr = sa + ((wm + mt * 16 + (lane & 15)) * HR128
                                      + kc * 16 + (lane >> 4) * 8) * 2;
                ldmx4(afr[mt][0], afr[mt][1], afr[mt][2], afr[mt][3], addr);
            }
            #pragma unroll
            for (int ng = 0; ng < 4; ng++) {
                uint32_t r0, r1, r2, r3;
                uint32_t addr = sb + ((wn + ng * 16 + (lane & 15)) * HR128
                                      + kc * 16 + (lane >> 4) * 8) * 2;
                ldmx4(r0, r1, r2, r3, addr);
                bfr[2 * ng][0] = r0; bfr[2 * ng + 1][0] = r1;
                bfr[2 * ng][1] = r2; bfr[2 * ng + 1][1] = r3;
            }
            #pragma unroll
            for (int mt = 0; mt < 2; mt++)
                #pragma unroll
                for (int nt = 0; nt < 8; nt++)
                    mma_f16(acc[mt][nt], afr[mt], bfr[nt]);
        }
    }

    // ---- fused row-LN epilogue ----
    __syncthreads();
    float* s_sum = (float*)smh;
    float* s_sq  = s_sum + 128;
    float* s_mu  = s_sq + 128;
    float* s_rs  = s_mu + 128;
    if (tid < 128) { s_sum[tid] = 0.f; s_sq[tid] = 0.f; }
    __syncthreads();

    #pragma unroll
    for (int mt = 0; mt < 2; mt++) {
        int rl = wm + mt * 16 + grp;
        float s0 = 0.f, q0 = 0.f, s1 = 0.f, q1 = 0.f;
        #pragma unroll
        for (int nt = 0; nt < 8; nt++) {
            int col = wn + nt * 8 + tig * 2;
            float b0 = __ldg(&bias[col]), b1 = __ldg(&bias[col + 1]);
            float c0 = acc[mt][nt][0] + b0, c1 = acc[mt][nt][1] + b1;
            float c2 = acc[mt][nt][2] + b0, c3 = acc[mt][nt][3] + b1;
            acc[mt][nt][0] = c0; acc[mt][nt][1] = c1;
            acc[mt][nt][2] = c2; acc[mt][nt][3] = c3;
            s0 += c0 + c1; q0 += c0 * c0 + c1 * c1;
            s1 += c2 + c3; q1 += c2 * c2 + c3 * c3;
        }
        #pragma unroll
        for (int o = 1; o < 4; o <<= 1) {
            s0 += __shfl_xor_sync(0xffffffffu, s0, o);
            q0 += __shfl_xor_sync(0xffffffffu, q0, o);
            s1 += __shfl_xor_sync(0xffffffffu, s1, o);
            q1 += __shfl_xor_sync(0xffffffffu, q1, o);
        }
        if (tig == 0) {
            atomicAdd(&s_sum[rl], s0);     atomicAdd(&s_sq[rl], q0);
            atomicAdd(&s_sum[rl + 8], s1); atomicAdd(&s_sq[rl + 8], q1);
        }
    }
    __syncthreads();
    if (tid < 128) {
        float m = s_sum[tid] * (1.f / 256.f);
        float var = s_sq[tid] * (1.f / 256.f) - m * m;
        s_mu[tid] = m;
        s_rs[tid] = rsqrtf(var + 1e-5f);
    }
    __syncthreads();

    #pragma unroll
    for (int mt = 0; mt < 2; mt++) {
        int rl = wm + mt * 16 + grp;
        float mu0 = s_mu[rl], rs0 = s_rs[rl];
        float mu1 = s_mu[rl + 8], rs1 = s_rs[rl + 8];
        int gr = bm + rl;
        #pragma unroll
        for (int nt = 0; nt < 8; nt++) {
            int col = wn + nt * 8 + tig * 2;
            float g0 = __ldg(&lng[col]), g1 = __ldg(&lng[col + 1]);
            float l0 = __ldg(&lnb[col]), l1 = __ldg(&lnb[col + 1]);
            float c0 = (acc[mt][nt][0] - mu0) * rs0 * g0 + l0;
            float c1 = (acc[mt][nt][1] - mu0) * rs0 * g1 + l1;
            float c2 = (acc[mt][nt][2] - mu1) * rs1 * g0 + l0;
            float c3 = (acc[mt][nt][3] - mu1) * rs1 * g1 + l1;
            *(__half2*)(Ch + (size_t)gr * Nn + col)       = __floats2half2_rn(c0, c1);
            *(__half2*)(Ch + (size_t)(gr + 8) * Nn + col) = __floats2half2_rn(c2, c3);
        }
    }
}

// ================= small-tile fp16 GEMM (slot path): 128x64, BK=32 ===========
// EPI 10: +bias -> fp32 (dual-source via blockIdx.z).
// EPI 11: relu(+bias) -> fp16.  EPI 12: +bias +res -> fp32 Cf AND fp16 Ch.
#define HROW 40
#define STG64_BYTES ((128 + 64) * HROW * 2)
#define H64_DSMEM (3 * STG64_BYTES)

template<int EPI>
__global__ void __launch_bounds__(256, 3)
hgemm64_kernel(const __half* __restrict__ A0, const __half* __restrict__ B0,
               int Nn, int K, float* __restrict__ Cf0, __half* __restrict__ Ch,
               const float* __restrict__ bias0, const float* __restrict__ res,
               const __half* A1, const __half* B1,
               float* Cf1, const float* bias1) {
    extern __shared__ __align__(16) __half smh[];
    uint32_t smb;
    asm("{ .reg .u64 t; cvta.to.shared.u64 t, %1; cvt.u32.u64 %0, t; }"
        : "=r"(smb) : "l"(smh));

    const __half* A = A0;
    const __half* Bw = B0;
    float* Cf = Cf0;
    const float* bias = bias0;
    if (EPI == 10 && blockIdx.z == 1) { A = A1; Bw = B1; Cf = Cf1; bias = bias1; }

    int tid = threadIdx.x;
    int lane = tid & 31;
    int warp = tid >> 5;
    int grp = lane >> 2, tig = lane & 3;
    int wm = (warp & 3) * 32;
    int wn = (warp >> 2) * 32;
    int bm = blockIdx.y * 128;
    int bn = blockIdx.x * 64;

    const __half* Abm = A + (size_t)bm * K;
    const __half* Bbn = Bw + (size_t)bn * K;

    float acc[2][4][4];
    #pragma unroll
    for (int mt = 0; mt < 2; mt++)
        #pragma unroll
        for (int nt = 0; nt < 4; nt++)
            #pragma unroll
            for (int i = 0; i < 4; i++) acc[mt][nt][i] = 0.f;

    int nit = K / 32;
    #pragma unroll
    for (int s = 0; s < 2; s++) {
        uint32_t base = smb + s * STG64_BYTES;
        #pragma unroll
        for (int j = 0; j < 2; j++) {
            int e = tid + j * 256;
            int r = e >> 2, c = e & 3;
            CP_ASYNC16(base + (r * HROW + c * 8) * 2, Abm + (size_t)r * K + s * 32 + c * 8);
        }
        {
            int r = tid >> 2, c = tid & 3;
            CP_ASYNC16(base + (128 * HROW + r * HROW + c * 8) * 2,
                       Bbn + (size_t)r * K + s * 32 + c * 8);
        }
        CP_COMMIT();
    }

    for (int it = 0; it < nit; it++) {
        CP_WAIT1();
        __syncthreads();
        uint32_t sa = smb + (it % 3) * STG64_BYTES;
        uint32_t sb = sa + 128 * HROW * 2;
        if (it + 2 < nit) {
            uint32_t base = smb + ((it + 2) % 3) * STG64_BYTES;
            #pragma unroll
            for (int j = 0; j < 2; j++) {
                int e = tid + j * 256;
                int r = e >> 2, c = e & 3;
                CP_ASYNC16(base + (r * HROW + c * 8) * 2,
                           Abm + (size_t)r * K + (it + 2) * 32 + c * 8);
            }
            {
                int r = tid >> 2, c = tid & 3;
                CP_ASYNC16(base + (128 * HROW + r * HROW + c * 8) * 2,
                           Bbn + (size_t)r * K + (it + 2) * 32 + c * 8);
            }
        }
        CP_COMMIT();

        #pragma unroll
        for (int kc = 0; kc < 2; kc++) {
            uint32_t afr[2][4], bfr[4][2];
            #pragma unroll
            for (int mt = 0; mt < 2; mt++) {
                uint32_t addr = sa + ((wm + mt * 16 + (lane & 15)) * HROW
                                      + kc * 16 + (lane >> 4) * 8) * 2;
                ldmx4(afr[mt][0], afr[mt][1], afr[mt][2], afr[mt][3], addr);
            }
            #pragma unroll
            for (int ng = 0; ng < 2; ng++) {
                uint32_t r0, r1, r2, r3;
                uint32_t addr = sb + ((wn + ng * 16 + (lane & 15)) * HROW
                                      + kc * 16 + (lane >> 4) * 8) * 2;
                ldmx4(r0, r1, r2, r3, addr);
                bfr[2 * ng][0] = r0; bfr[2 * ng + 1][0] = r1;
                bfr[2 * ng][1] = r2; bfr[2 * ng + 1][1] = r3;
            }
            #pragma unroll
            for (int mt = 0; mt < 2; mt++)
                #pragma unroll
                for (int nt = 0; nt < 4; nt++)
                    mma_f16(acc[mt][nt], afr[mt], bfr[nt]);
        }
    }

    #pragma unroll
    for (int mt = 0; mt < 2; mt++) {
        int r0 = bm + wm + mt * 16 + grp;
        #pragma unroll
        for (int nt = 0; nt < 4; nt++) {
            int col = bn + wn + nt * 8 + tig * 2;
            float b0 = __ldg(&bias[col]), b1 = __ldg(&bias[col + 1]);
            float c0 = acc[mt][nt][0] + b0, c1 = acc[mt][nt][1] + b1;
            float c2 = acc[mt][nt][2] + b0, c3 = acc[mt][nt][3] + b1;
            if (EPI == 10) {
                *(float2*)(Cf + (size_t)r0 * Nn + col)       = make_float2(c0, c1);
                *(float2*)(Cf + (size_t)(r0 + 8) * Nn + col) = make_float2(c2, c3);
            } else if (EPI == 11) {
                c0 = fmaxf(c0, 0.f); c1 = fmaxf(c1, 0.f);
                c2 = fmaxf(c2, 0.f); c3 = fmaxf(c3, 0.f);
                *(__half2*)(Ch + (size_t)r0 * Nn + col)       = __floats2half2_rn(c0, c1);
                *(__half2*)(Ch + (size_t)(r0 + 8) * Nn + col) = __floats2half2_rn(c2, c3);
            } else {   // EPI 12: residual + dual store
                float2 ra = *(const float2*)(res + (size_t)r0 * Nn + col);
                float2 rb = *(const float2*)(res + (size_t)(r0 + 8) * Nn + col);
                c0 += ra.x; c1 += ra.y; c2 += rb.x; c3 += rb.y;
                *(float2*)(Cf + (size_t)r0 * Nn + col)       = make_float2(c0, c1);
                *(float2*)(Cf + (size_t)(r0 + 8) * Nn + col) = make_float2(c2, c3);
                *(__half2*)(Ch + (size_t)r0 * Nn + col)       = __floats2half2_rn(c0, c1);
                *(__half2*)(Ch + (size_t)(r0 + 8) * Nn + col) = __floats2half2_rn(c2, c3);
            }
        }
    }
}

// ================= prep / small kernels =================
__global__ void ln_stats_f2h_kernel(const float* __restrict__ x, __half* __restrict__ xh) {
    int row = blockIdx.x * 8 + (threadIdx.x >> 5);
    int lane = threadIdx.x & 31;
    const float* p = x + (size_t)row * FDIN;
    __half* ph = xh + (size_t)row * FDIN;
    float v[24];
    float s = 0.f, ss = 0.f;
    #pragma unroll
    for (int k = 0; k < 24; k++) {
        v[k] = p[lane + 32 * k];
        s += v[k];
        ss += v[k] * v[k];
    }
    #pragma unroll
    for (int k = 0; k < 24; k++) ph[lane + 32 * k] = __float2half(v[k]);
    #pragma unroll
    for (int o = 16; o; o >>= 1) {
        s  += __shfl_xor_sync(0xffffffffu, s, o);
        ss += __shfl_xor_sync(0xffffffffu, ss, o);
    }
    float m = s * (1.f / FDIN);
    float var = ss * (1.f / FDIN) - m * m;
    if (lane == 0) { g_mean[row] = m; g_rstd[row] = rsqrtf(var + 1e-5f); }
}

// dual f2h
__global__ void conv2_f2h_kernel(const float* __restrict__ in0, __half* __restrict__ out0,
                                 const float* __restrict__ in1, __half* __restrict__ out1,
                                 int halfBlocks) {
    const float* in = in0;
    __half* out = out0;
    int bx = blockIdx.x;
    if (bx >= halfBlocks) { in = in1; out = out1; bx -= halfBlocks; }
    size_t i = ((size_t)bx * 256 + threadIdx.x) * 4;
    float4 v = *(const float4*)(in + i);
    *(__half2*)(out + i)     = __floats2half2_rn(v.x, v.y);
    *(__half2*)(out + i + 2) = __floats2half2_rn(v.z, v.w);
}

__global__ void trans_h_kernel(const float* __restrict__ in, __half* __restrict__ out,
                               int R, int C, const float* __restrict__ scale) {
    __shared__ float t[32][33];
    int bx = blockIdx.x * 32, by = blockIdx.y * 32;
    int x = bx + threadIdx.x;
    #pragma unroll
    for (int j = 0; j < 32; j += 8) {
        int y = by + threadIdx.y + j;
        float s = scale ? scale[y] : 1.f;
        t[threadIdx.y + j][threadIdx.x] = in[(size_t)y * C + x] * s;
    }
    __syncthreads();
    int x2 = by + threadIdx.x;
    #pragma unroll
    for (int j = 0; j < 32; j += 8) {
        int y2 = bx + threadIdx.y + j;
        out[(size_t)y2 * R + x2] = __float2half(t[threadIdx.x][threadIdx.y + j]);
    }
}

__global__ void trans_f_kernel(const float* __restrict__ in, float* __restrict__ out,
                               int R, int C) {
    __shared__ float t[32][33];
    int bx = blockIdx.x * 32, by = blockIdx.y * 32;
    int x = bx + threadIdx.x;
    #pragma unroll
    for (int j = 0; j < 32; j += 8)
        t[threadIdx.y + j][threadIdx.x] = in[(size_t)(by + threadIdx.y + j) * C + x];
    __syncthreads();
    int x2 = by + threadIdx.x;
    #pragma unroll
    for (int j = 0; j < 32; j += 8)
        out[(size_t)(bx + threadIdx.y + j) * R + x2] = t[threadIdx.x][threadIdx.y + j];
}

__global__ void wkv_h_kernel(const float* __restrict__ wk, const float* __restrict__ wv) {
    int i = blockIdx.x * 256 + threadIdx.x;
    g_wkvh[i] = __float2half(wk[i]);
    g_wkvh[DD * DD + i] = __float2half(wv[i]);
}

__global__ void prep_sums_kernel(const float* __restrict__ w1,
                                 const float* __restrict__ g,
                                 const float* __restrict__ b,
                                 const float* __restrict__ b1) {
    int n = blockIdx.x * 256 + threadIdx.x;
    int k0 = blockIdx.y * 96;
    float s1 = 0.f, s2 = 0.f;
    #pragma unroll 8
    for (int k = k0; k < k0 + 96; k++) {
        float w = w1[(size_t)k * FDIN + n];
        s1 += g[k] * w;
        s2 += b[k] * w;
    }
    if (blockIdx.y == 0) s2 += b1[n];
    atomicAdd(&g_gB[n], s1);
    atomicAdd(&g_bBp[n], s2);
}

__global__ void slots_init_kernel(const float* __restrict__ si) {
    int i = blockIdx.x * 256 + threadIdx.x;
    float v = si[i & (NS * DD - 1)];
    g_slots[i] = v;
    g_slotsh[i] = __float2half(v);
}

__device__ __forceinline__ float2 block_meanvar_256(float v, float* r1, float* r2) {
    float s = v, q = v * v;
    #pragma unroll
    for (int o = 16; o; o >>= 1) {
        s += __shfl_xor_sync(0xffffffffu, s, o);
        q += __shfl_xor_sync(0xffffffffu, q, o);
    }
    int w = threadIdx.x >> 5, lane = threadIdx.x & 31;
    if (lane == 0) { r1[w] = s; r2[w] = q; }
    __syncthreads();
    float sum = 0.f, sq = 0.f;
    #pragma unroll
    for (int i = 0; i < 8; i++) { sum += r1[i]; sq += r2[i]; }
    __syncthreads();
    float m = sum * (1.f / 256.f);
    float var = sq * (1.f / 256.f) - m * m;
    return make_float2(m, rsqrtf(var + 1e-5f));
}

__global__ void qproj_kernel(const float* __restrict__ ng, const float* __restrict__ nb) {
    __shared__ float sln[DD];
    __shared__ float r1[8], r2[8];
    int row = blockIdx.x, tid = threadIdx.x;
    float v = g_slots[row * DD + tid];
    float2 mv = block_meanvar_256(v, r1, r2);
    sln[tid] = (v - mv.x) * mv.y * ng[tid] + nb[tid];
    g_U[row * DD + tid] = 0.f;
    if (tid == 0) g_rowsum[row] = 0.f;
    __syncthreads();
    float acc = 0.f;
    #pragma unroll 8
    for (int d = 0; d < DD; d++) acc += sln[d] * g_wqT[d * DD + tid];
    g_q[row * DD + tid] = acc;
}

// attention: packed f32x2 FMA in dot and update phases
__global__ void __launch_bounds__(256)
attn_kernel() {
    int b = blockIdx.x, ch = blockIdx.y;
    int warp = threadIdx.x >> 5, lane = threadIdx.x & 31;
    __shared__ float qs[NS * DD];
    __shared__ float dots[8][NS];
    __shared__ float aw[8][NS];
    for (int i = threadIdx.x; i < NS * DD; i += 256) qs[i] = g_q[b * NS * DD + i];
    __syncthreads();
    unsigned long long qp[4];
    #pragma unroll
    for (int k = 0; k < 4; k++)
        qp[k] = pk2(qs[warp * DD + 2 * (lane + 32 * k)],
                    qs[warp * DD + 2 * (lane + 32 * k) + 1]);
    unsigned long long uacc[4];
    #pragma unroll
    for (int k = 0; k < 4; k++) uacc[k] = pk2(0.f, 0.f);
    float rsum = 0.f;
    const float scale = 0.0625f;
    int t0 = ch * 256;
    const __half* kvb = g_kvh + ((size_t)b * NTOK + t0) * 512;

    for (int tt = 0; tt < 256; tt += 8) {
        #pragma unroll
        for (int u = 0; u < 8; u++) {
            const __half2* kp = (const __half2*)(kvb + (size_t)(tt + u) * 512);
            unsigned long long dacc = pk2(0.f, 0.f);
            #pragma unroll
            for (int k = 0; k < 4; k++) {
                float2 kv2 = __half22float2(kp[lane + 32 * k]);
                FMA2(dacc, qp[k], pk2(kv2.x, kv2.y));
            }
            float2 dd = upk2(dacc);
            float d = dd.x + dd.y;
            #pragma unroll
            for (int o = 16; o; o >>= 1) d += __shfl_xor_sync(0xffffffffu, d, o);
            if (lane == 0) dots[u][warp] = d * scale;
        }
        __syncthreads();
        if (threadIdx.x < 64) {
            int u = threadIdx.x >> 3, s = threadIdx.x & 7;
            float mx = -1e30f;
            #pragma unroll
            for (int s2 = 0; s2 < NS; s2++) mx = fmaxf(mx, dots[u][s2]);
            float e = expf(dots[u][s] - mx);
            float sum = e;
            #pragma unroll
            for (int o = 1; o < 8; o <<= 1) sum += __shfl_xor_sync(0xffffffffu, sum, o);
            aw[u][s] = e / sum + 1e-8f;
        }
        __syncthreads();
        #pragma unroll
        for (int u = 0; u < 8; u++) {
            float a = aw[u][warp];
            unsigned long long aa = pk2(a, a);
            const __half2* vp = (const __half2*)(kvb + (size_t)(tt + u) * 512 + 256);
            #pragma unroll
            for (int k = 0; k < 4; k++) {
                float2 vv = __half22float2(vp[lane + 32 * k]);
                FMA2(uacc[k], aa, pk2(vv.x, vv.y));
            }
            rsum += a;
        }
        __syncthreads();
    }
    float* up = g_U + (b * NS + warp) * DD;
    #pragma unroll
    for (int k = 0; k < 4; k++) {
        float2 uu = upk2(uacc[k]);
        atomicAdd(&up[2 * (lane + 32 * k)], uu.x);
        atomicAdd(&up[2 * (lane + 32 * k) + 1], uu.y);
    }
    if (lane == 0) atomicAdd(&g_rowsum[b * NS + warp], rsum);
}

__global__ void updfin_kernel() {
    int i = blockIdx.x * 256 + threadIdx.x;
    g_updh[i] = __float2half(g_U[i] / g_rowsum[i >> 8]);
}

__global__ void gru_pw_kernel(const float* __restrict__ mlng,
                              const float* __restrict__ mlnb) {
    __shared__ float r1[8], r2[8];
    int row = blockIdx.x, tid = threadIdx.x;
    const float* gi = g_gi + row * 3 * DD;
    const float* gh = g_gh + row * 3 * DD;
    float ir = gi[tid], iz = gi[tid + 256], inn = gi[tid + 512];
    float hr = gh[tid], hz = gh[tid + 256], hn = gh[tid + 512];
    float sprev = g_slots[row * DD + tid];
    float r = 1.f / (1.f + expf(-(ir + hr)));
    float z = 1.f / (1.f + expf(-(iz + hz)));
    float n = tanhf(inn + r * hn);
    float h = (1.f - z) * n + z * sprev;
    g_hbuf[row * DD + tid] = h;
    float2 mv = block_meanvar_256(h, r1, r2);
    g_mlpinh[row * DD + tid] = __float2half((h - mv.x) * mv.y * mlng[tid] + mlnb[tid]);
}

// ================= launch =================
extern "C" void kernel_launch(void* const* d_in, const int* in_sizes, int n_in,
                              void* d_out, int out_size) {
    const float* inputs   = (const float*)d_in[0];
    const float* slots_in = (const float*)d_in[1];
    const float* ln1g = (const float*)d_in[2];
    const float* ln1b = (const float*)d_in[3];
    const float* w1   = (const float*)d_in[4];
    const float* b1   = (const float*)d_in[5];
    const float* w2   = (const float*)d_in[6];
    const float* b2   = (const float*)d_in[7];
    const float* ln2g = (const float*)d_in[8];
    const float* ln2b = (const float*)d_in[9];
    const float* wq   = (const float*)d_in[10];
    const float* wk   = (const float*)d_in[11];
    const float* wv   = (const float*)d_in[12];
    const float* normg = (const float*)d_in[13];
    const float* normb = (const float*)d_in[14];
    const float* gwih = (const float*)d_in[15];
    const float* gwhh = (const float*)d_in[16];
    const float* gbih = (const float*)d_in[17];
    const float* gbhh = (const float*)d_in[18];
    const float* mlng = (const float*)d_in[19];
    const float* mlnb = (const float*)d_in[20];
    const float* mw1  = (const float*)d_in[21];
    const float* mb1  = (const float*)d_in[22];
    const float* mw2  = (const float*)d_in[23];
    const float* mb2  = (const float*)d_in[24];
    float* out = (float*)d_out;

    __half *p_inh, *p_h1h, *p_featsh, *p_kvh, *p_w1h, *p_w2h, *p_wkvh;
    __half *p_wihh, *p_whhh, *p_mw1h, *p_mw2h, *p_updh, *p_mlpinh, *p_hhh, *p_slotsh;
    float *p_wqT, *p_slots, *p_gi, *p_gh, *p_hbuf, *p_gB, *p_bBp;
    cudaGetSymbolAddress((void**)&p_inh,    g_inh);
    cudaGetSymbolAddress((void**)&p_h1h,    g_h1h);
    cudaGetSymbolAddress((void**)&p_featsh, g_featsh);
    cudaGetSymbolAddress((void**)&p_kvh,    g_kvh);
    cudaGetSymbolAddress((void**)&p_w1h,    g_w1h);
    cudaGetSymbolAddress((void**)&p_w2h,    g_w2h);
    cudaGetSymbolAddress((void**)&p_wkvh,   g_wkvh);
    cudaGetSymbolAddress((void**)&p_wihh,   g_wihh);
    cudaGetSymbolAddress((void**)&p_whhh,   g_whhh);
    cudaGetSymbolAddress((void**)&p_mw1h,   g_mw1h);
    cudaGetSymbolAddress((void**)&p_mw2h,   g_mw2h);
    cudaGetSymbolAddress((void**)&p_updh,   g_updh);
    cudaGetSymbolAddress((void**)&p_mlpinh, g_mlpinh);
    cudaGetSymbolAddress((void**)&p_hhh,    g_hhh);
    cudaGetSymbolAddress((void**)&p_slotsh, g_slotsh);
    cudaGetSymbolAddress((void**)&p_wqT,    g_wqT);
    cudaGetSymbolAddress((void**)&p_slots,  g_slots);
    cudaGetSymbolAddress((void**)&p_gi,     g_gi);
    cudaGetSymbolAddress((void**)&p_gh,     g_gh);
    cudaGetSymbolAddress((void**)&p_hbuf,   g_hbuf);
    cudaGetSymbolAddress((void**)&p_gB,     g_gB);
    cudaGetSymbolAddress((void**)&p_bBp,    g_bBp);

    cudaFuncSetAttribute(hgemm128_kernel<1>, cudaFuncAttributeMaxDynamicSharedMemorySize, H128_DSMEM);
    cudaFuncSetAttribute(hgemm128_kernel<3>, cudaFuncAttributeMaxDynamicSharedMemorySize, H128_DSMEM);
    cudaFuncSetAttribute(hgemm2ln_kernel,    cudaFuncAttributeMaxDynamicSharedMemorySize, H256_DSMEM);

    dim3 tb(32, 8);
    cudaMemsetAsync(p_gB, 0, FDIN * sizeof(float));
    cudaMemsetAsync(p_bBp, 0, FDIN * sizeof(float));
    // 0: fused LN stats + fp16 conversion of inputs
    ln_stats_f2h_kernel<<<MROWS / 8, 256>>>(inputs, p_inh);
    // 1: w1 -> [N][K] fp16 scaled by ln1g
    trans_h_kernel<<<dim3(FDIN / 32, FDIN / 32), tb>>>(w1, p_w1h, FDIN, FDIN, ln1g);
    // 2: epilogue fold vectors
    prep_sums_kernel<<<dim3(FDIN / 256, 8), 256>>>(w1, ln1g, ln1b, b1);
    // 3: GEMM1 (128x128, BK=64)   << ncu window
    hgemm128_kernel<1><<<dim3(FDIN / 128, MROWS / 128), 256, H128_DSMEM>>>(
        p_inh, p_w1h, FDIN, FDIN, p_h1h);
    // 4: w2 -> [N][K] fp16
    trans_h_kernel<<<dim3(DD / 32, FDIN / 32), tb>>>(w2, p_w2h, FDIN, DD, nullptr);
    // 5: GEMM2 fused row-LN: feats = LN(h1 @ w2 + b2) -> fp16
    hgemm2ln_kernel<<<dim3(1, MROWS / 128), 512, H256_DSMEM>>>(
        p_h1h, p_w2h, FDIN, p_featsh, b2, ln2g, ln2b);
    // 6: wk|wv -> fp16
    wkv_h_kernel<<<DD * DD / 256, 256>>>(wk, wv);
    // 7: KV GEMM -> fp16
    hgemm128_kernel<3><<<dim3(2 * DD / 128, MROWS / 128), 256, H128_DSMEM>>>(
        p_featsh, p_wkvh, 2 * DD, DD, p_kvh);

    // slot-path weight prep
    trans_f_kernel<<<dim3(DD / 32, DD / 32), tb>>>(wq, p_wqT, DD, DD);
    conv2_f2h_kernel<<<2 * (3 * DD * DD / 1024), 256>>>(gwih, p_wihh, gwhh, p_whhh,
                                                        3 * DD * DD / 1024);
    trans_h_kernel<<<dim3(4 * DD / 32, DD / 32), tb>>>(mw1, p_mw1h, DD, 4 * DD, nullptr);
    trans_h_kernel<<<dim3(DD / 32, 4 * DD / 32), tb>>>(mw2, p_mw2h, 4 * DD, DD, nullptr);
    slots_init_kernel<<<SROWS * DD / 256, 256>>>(slots_in);

    for (int t = 0; t < ITERS; t++) {
        qproj_kernel<<<SROWS, 256>>>(normg, normb);
        attn_kernel<<<dim3(BNUM, 16), 256>>>();
        updfin_kernel<<<SROWS, 256>>>();
        hgemm64_kernel<10><<<dim3(3 * DD / 64, SROWS / 128, 2), 256, H64_DSMEM>>>(
            p_updh, p_wihh, 3 * DD, DD, p_gi, nullptr, gbih, nullptr,
            p_slotsh, p_whhh, p_gh, gbhh);
        gru_pw_kernel<<<SROWS, 256>>>(mlng, mlnb);
        hgemm64_kernel<11><<<dim3(4 * DD / 64, SROWS / 128), 256, H64_DSMEM>>>(
            p_mlpinh, p_mw1h, 4 * DD, DD, nullptr, p_hhh, mb1, nullptr,
            nullptr, nullptr, nullptr, nullptr);
        float* dst = (t == ITERS - 1) ? out : p_slots;
        hgemm64_kernel<12><<<dim3(DD / 64, SROWS / 128), 256, H64_DSMEM>>>(
            p_hhh, p_mw2h, DD, 4 * DD, dst, p_slotsh, mb2, p_hbuf,
            nullptr, nullptr, nullptr, nullptr);
    }
}